// round 8
// baseline (speedup 1.0000x reference)
#include <cuda_runtime.h>
#include <cuda_bf16.h>
#include <cstdint>

// ---------------- problem constants ----------------
#define BATCH 64
#define LSEQ  1024
#define EDIM  320
#define HDIM  480
#define CDIM  32
#define NLAYER 7
#define MTOK  (BATCH*LSEQ)   // 65536

// ---------------- device scratch ----------------
__device__ float          g_bm[NLAYER*HDIM];
__device__ float          g_bias[NLAYER*HDIM];
__device__ __nv_bfloat16  g_w0[HDIM*EDIM];
__device__ __nv_bfloat16  g_wmid[(NLAYER-1)*HDIM*HDIM];
__device__ __nv_bfloat16  g_wlast[EDIM*HDIM];
__device__ float          g_xnf[(size_t)MTOK*EDIM];
__device__ __nv_bfloat16  g_xnb[(size_t)MTOK*EDIM];
__device__ __nv_bfloat16  g_tA[(size_t)MTOK*HDIM];
__device__ __nv_bfloat16  g_tB[(size_t)MTOK*HDIM];
__device__ float          g_xgf[(size_t)MTOK*EDIM];

// ---------------- small kernels ----------------

__global__ void bm_kernel(const float* __restrict__ snr,
                          const float* __restrict__ w1, const float* __restrict__ b1,
                          const float* __restrict__ w2, const float* __restrict__ b2,
                          const float* __restrict__ w3, const float* __restrict__ b3)
{
    __shared__ float h1[HDIM];
    __shared__ float h2[HDIM];
    const int j = threadIdx.x;
    const float s = snr[0];
    for (int i = 0; i < NLAYER; i++) {
        if (j < HDIM)
            h1[j] = fmaxf(0.f, s * w1[i*HDIM + j] + b1[i*HDIM + j]);
        __syncthreads();
        if (j < HDIM) {
            const float* wp = w2 + ((size_t)i*HDIM + j) * HDIM;
            float acc = b2[i*HDIM + j];
            for (int k = 0; k < HDIM; k++) acc += wp[k] * h1[k];
            h2[j] = fmaxf(0.f, acc);
        }
        __syncthreads();
        if (j < HDIM) {
            const float* wp = w3 + ((size_t)i*HDIM + j) * HDIM;
            float acc = b3[i*HDIM + j];
            for (int k = 0; k < HDIM; k++) acc += wp[k] * h2[k];
            g_bm[i*HDIM + j] = 1.f / (1.f + expf(-acc));
        }
        __syncthreads();
    }
}

__global__ void fold_row_kernel(const float* __restrict__ w, const float* __restrict__ b,
                                const float* __restrict__ bm,
                                __nv_bfloat16* __restrict__ wo, float* __restrict__ bo,
                                int rows, int cols)
{
    const int stride = gridDim.x * blockDim.x;
    const int g = blockIdx.x * blockDim.x + threadIdx.x;
    for (int idx = g; idx < rows*cols; idx += stride)
        wo[idx] = __float2bfloat16(w[idx] * bm[idx / cols]);
    for (int j = g; j < rows; j += stride)
        bo[j] = b[j] * bm[j];
}

__global__ void conv_kernel(const float* __restrict__ w, __nv_bfloat16* __restrict__ wo, int n)
{
    const int stride = gridDim.x * blockDim.x;
    for (int idx = blockIdx.x * blockDim.x + threadIdx.x; idx < n; idx += stride)
        wo[idx] = __float2bfloat16(w[idx]);
}

__global__ void ln_kernel(const float* __restrict__ x,
                          const float* __restrict__ w, const float* __restrict__ b)
{
    const int warp = threadIdx.x >> 5;
    const int lane = threadIdx.x & 31;
    const size_t t = (size_t)blockIdx.x * 8 + warp;
    const float* xp = x + t * EDIM;
    float v[10];
    float s = 0.f, s2 = 0.f;
    #pragma unroll
    for (int i = 0; i < 10; i++) {
        v[i] = xp[lane + 32*i];
        s  += v[i];
        s2 += v[i]*v[i];
    }
    #pragma unroll
    for (int o = 16; o > 0; o >>= 1) {
        s  += __shfl_xor_sync(0xffffffffu, s,  o);
        s2 += __shfl_xor_sync(0xffffffffu, s2, o);
    }
    const float mu  = s  * (1.f/EDIM);
    const float var = s2 * (1.f/EDIM) - mu*mu;
    const float inv = 1.f / sqrtf(var + 1e-5f);
    #pragma unroll
    for (int i = 0; i < 10; i++) {
        const int c = lane + 32*i;
        const float y = (v[i] - mu) * inv * w[c] + b[c];
        g_xnf[t*EDIM + c] = y;
        g_xnb[t*EDIM + c] = __float2bfloat16(y);
    }
}

// ---------------- GEMM: C[M,N] = A[M,K] @ W[N,K]^T + bias, mma.sync bf16 ----------------
#define BM_T 128
#define BK_T 32
#define LDT  (BK_T + 8)
#define STAGES 3

__device__ __forceinline__ void cp16(uint32_t s, const void* g) {
    asm volatile("cp.async.cg.shared.global [%0], [%1], 16;" :: "r"(s), "l"(g));
}
__device__ __forceinline__ void ldm4(uint32_t a, uint32_t& r0, uint32_t& r1, uint32_t& r2, uint32_t& r3) {
    asm volatile("ldmatrix.sync.aligned.m8n8.x4.shared.b16 {%0,%1,%2,%3}, [%4];"
                 : "=r"(r0), "=r"(r1), "=r"(r2), "=r"(r3) : "r"(a));
}
__device__ __forceinline__ void mma16816(float* c, const uint32_t* a, const uint32_t* b) {
    asm volatile("mma.sync.aligned.m16n8k16.row.col.f32.bf16.bf16.f32 "
                 "{%0,%1,%2,%3}, {%4,%5,%6,%7}, {%8,%9}, {%0,%1,%2,%3};"
                 : "+f"(c[0]), "+f"(c[1]), "+f"(c[2]), "+f"(c[3])
                 : "r"(a[0]), "r"(a[1]), "r"(a[2]), "r"(a[3]), "r"(b[0]), "r"(b[1]));
}

// EPI: 0 = bias -> bf16 ; 1 = sigmoid(.+bias)*xn -> fp32
template<int BN, int EPI>
__global__ __launch_bounds__(256, 2) void gemm_k(
    const __nv_bfloat16* __restrict__ A, const __nv_bfloat16* __restrict__ W,
    const float* __restrict__ bias, const float* __restrict__ xnf,
    void* __restrict__ Cout, int M, int N, int K)
{
    constexpr int NI = BN / 16;           // n8 tiles per warp (warp covers BN/2 cols)
    constexpr int ASTG = BM_T * LDT;      // elements per A stage
    constexpr int BSTG = BN * LDT;        // elements per B stage

    extern __shared__ __align__(16) __nv_bfloat16 smem[];
    __nv_bfloat16* Asm = smem;                  // [STAGES][ASTG]
    __nv_bfloat16* Bsm = smem + STAGES * ASTG;  // [STAGES][BSTG]

    const int tid  = threadIdx.x;
    const int lane = tid & 31;
    const int warp = tid >> 5;
    const int wr = warp & 3;   // 4 warps along M
    const int wc = warp >> 2;  // 2 warps along N

    const uint32_t sA = (uint32_t)__cvta_generic_to_shared(Asm);
    const uint32_t sB = (uint32_t)__cvta_generic_to_shared(Bsm);
    const size_t Arow0 = (size_t)blockIdx.x * BM_T;
    const size_t Brow0 = (size_t)blockIdx.y * BN;
    const int KT = K / BK_T;

    auto load_st = [&](int kt, int buf) {
        const __nv_bfloat16* Ag = A + Arow0 * K + (size_t)kt * BK_T;
        const uint32_t sa = sA + buf * (ASTG * 2);
        #pragma unroll 2
        for (int id = tid; id < BM_T * 4; id += 256) {
            const int r = id >> 2, c = (id & 3) * 8;
            cp16(sa + (r * LDT + c) * 2, Ag + (size_t)r * K + c);
        }
        const __nv_bfloat16* Bg = W + Brow0 * K + (size_t)kt * BK_T;
        const uint32_t sb = sB + buf * (BSTG * 2);
        #pragma unroll 2
        for (int id = tid; id < BN * 4; id += 256) {
            const int r = id >> 2, c = (id & 3) * 8;
            cp16(sb + (r * LDT + c) * 2, Bg + (size_t)r * K + c);
        }
        asm volatile("cp.async.commit_group;");
    };

    float acc[2][NI][4];
    #pragma unroll
    for (int mi = 0; mi < 2; mi++)
        #pragma unroll
        for (int ni = 0; ni < NI; ni++)
            #pragma unroll
            for (int e = 0; e < 4; e++) acc[mi][ni][e] = 0.f;

    // prologue: stages 0,1
    load_st(0, 0);
    load_st(1, 1);

    for (int kt = 0; kt < KT; kt++) {
        // ensure group kt complete (groups committed so far: min(kt+1, KT-1) beyond kt)
        if (kt < KT - 1) asm volatile("cp.async.wait_group 1;");
        else             asm volatile("cp.async.wait_group 0;");
        __syncthreads();

        // issue next load early (into buffer freed by iteration kt-1)
        if (kt + 2 < KT) load_st(kt + 2, (kt + 2) % STAGES);

        const int buf = kt % STAGES;
        const uint32_t baseA = sA + buf * (ASTG * 2);
        const uint32_t baseB = sB + buf * (BSTG * 2);
        #pragma unroll
        for (int ks = 0; ks < 2; ks++) {
            uint32_t af[2][4];
            #pragma unroll
            for (int mi = 0; mi < 2; mi++) {
                const int row = wr * 32 + mi * 16 + (lane & 15);
                const int col = ks * 16 + (lane >> 4) * 8;
                ldm4(baseA + (row * LDT + col) * 2, af[mi][0], af[mi][1], af[mi][2], af[mi][3]);
            }
            uint32_t bf[NI][2];
            #pragma unroll
            for (int np = 0; np < NI / 2; np++) {
                const int row = wc * (BN / 2) + np * 16 + (lane & 7) + ((lane >> 4) << 3);
                const int col = ks * 16 + (((lane >> 3) & 1) << 3);
                ldm4(baseB + (row * LDT + col) * 2,
                     bf[2*np][0], bf[2*np][1], bf[2*np+1][0], bf[2*np+1][1]);
            }
            #pragma unroll
            for (int mi = 0; mi < 2; mi++)
                #pragma unroll
                for (int ni = 0; ni < NI; ni++)
                    mma16816(acc[mi][ni], af[mi], bf[ni]);
        }
    }

    // epilogue
    const size_t mb = Arow0 + wr * 32;
    const int nb = (int)Brow0 + wc * (BN / 2);
    #pragma unroll
    for (int mi = 0; mi < 2; mi++) {
        #pragma unroll
        for (int ni = 0; ni < NI; ni++) {
            const size_t m0 = mb + mi * 16 + (lane >> 2);
            const int n0 = nb + ni * 8 + (lane & 3) * 2;
            #pragma unroll
            for (int e = 0; e < 4; e++) {
                const size_t m = m0 + ((e >= 2) ? 8 : 0);
                const int n = n0 + (e & 1);
                const float v = acc[mi][ni][e] + bias[n];
                if (EPI == 0) {
                    ((__nv_bfloat16*)Cout)[m * N + n] = __float2bfloat16(v);
                } else {
                    const float sg = 1.f / (1.f + __expf(-v));
                    ((float*)Cout)[m * N + n] = sg * xnf[m * N + n];
                }
            }
        }
    }
}

// ---------------- head GEMM: fp32, M=65536 N=32 K=320 ----------------
__global__ __launch_bounds__(256, 2) void head_kernel(
    const float* __restrict__ A, const float* __restrict__ W,
    const float* __restrict__ bias, float* __restrict__ out)
{
    __shared__ float ws[EDIM * CDIM];     // 40 KB
    __shared__ float as[32 * 128];        // 16 KB

    const int tid = threadIdx.x;
    for (int i = tid; i < EDIM * CDIM; i += 256) {
        const int c = i & 31;
        const int k = i >> 5;
        ws[k * CDIM + c] = W[c * EDIM + k];
    }

    const size_t row0 = (size_t)blockIdx.x * 128;
    const int rg = tid >> 3;
    const int cg = tid & 7;

    float acc[4][4];
    #pragma unroll
    for (int i = 0; i < 4; i++)
        #pragma unroll
        for (int j = 0; j < 4; j++) acc[i][j] = 0.f;

    for (int k0 = 0; k0 < EDIM; k0 += 32) {
        __syncthreads();
        #pragma unroll
        for (int i = 0; i < 4; i++) {
            const int idx = tid + 256 * i;
            const int r  = idx & 127;
            const int kq = idx >> 7;
            const float4 v = *(const float4*)(A + (row0 + r) * EDIM + k0 + kq * 4);
            as[(kq * 4 + 0) * 128 + r] = v.x;
            as[(kq * 4 + 1) * 128 + r] = v.y;
            as[(kq * 4 + 2) * 128 + r] = v.z;
            as[(kq * 4 + 3) * 128 + r] = v.w;
        }
        __syncthreads();
        #pragma unroll
        for (int k = 0; k < 32; k++) {
            const float4 av = *(const float4*)(as + k * 128 + rg * 4);
            const float4 bv = *(const float4*)(ws + (k0 + k) * CDIM + cg * 4);
            acc[0][0] += av.x * bv.x; acc[0][1] += av.x * bv.y;
            acc[0][2] += av.x * bv.z; acc[0][3] += av.x * bv.w;
            acc[1][0] += av.y * bv.x; acc[1][1] += av.y * bv.y;
            acc[1][2] += av.y * bv.z; acc[1][3] += av.y * bv.w;
            acc[2][0] += av.z * bv.x; acc[2][1] += av.z * bv.y;
            acc[2][2] += av.z * bv.z; acc[2][3] += av.z * bv.w;
            acc[3][0] += av.w * bv.x; acc[3][1] += av.w * bv.y;
            acc[3][2] += av.w * bv.z; acc[3][3] += av.w * bv.w;
        }
    }

    const float4 bv = *(const float4*)(bias + cg * 4);
    #pragma unroll
    for (int i = 0; i < 4; i++) {
        float4 o;
        o.x = acc[i][0] + bv.x;
        o.y = acc[i][1] + bv.y;
        o.z = acc[i][2] + bv.z;
        o.w = acc[i][3] + bv.w;
        *(float4*)(out + (row0 + rg * 4 + i) * CDIM + cg * 4) = o;
    }
}

// ---------------- launch ----------------
extern "C" void kernel_launch(void* const* d_in, const int* in_sizes, int n_in,
                              void* d_out, int out_size)
{
    (void)in_sizes; (void)n_in; (void)out_size;
    const float* x       = (const float*)d_in[0];
    const float* snr     = (const float*)d_in[1];
    const float* norm_w  = (const float*)d_in[2];
    const float* norm_b  = (const float*)d_in[3];
    const float* sm0_w   = (const float*)d_in[4];
    const float* sm0_b   = (const float*)d_in[5];
    const float* smm_w   = (const float*)d_in[6];
    const float* smm_b   = (const float*)d_in[7];
    const float* sml_w   = (const float*)d_in[8];
    const float* sml_b   = (const float*)d_in[9];
    const float* bm_w1   = (const float*)d_in[10];
    const float* bm_b1   = (const float*)d_in[11];
    const float* bm_w2   = (const float*)d_in[12];
    const float* bm_b2   = (const float*)d_in[13];
    const float* bm_w3   = (const float*)d_in[14];
    const float* bm_b3   = (const float*)d_in[15];
    const float* head_w  = (const float*)d_in[16];
    const float* head_b  = (const float*)d_in[17];

    float *p_bm, *p_bias, *p_xnf, *p_xgf;
    __nv_bfloat16 *p_w0, *p_wmid, *p_wlast, *p_xnb, *p_tA, *p_tB;
    cudaGetSymbolAddress((void**)&p_bm,    g_bm);
    cudaGetSymbolAddress((void**)&p_bias,  g_bias);
    cudaGetSymbolAddress((void**)&p_xnf,   g_xnf);
    cudaGetSymbolAddress((void**)&p_xgf,   g_xgf);
    cudaGetSymbolAddress((void**)&p_w0,    g_w0);
    cudaGetSymbolAddress((void**)&p_wmid,  g_wmid);
    cudaGetSymbolAddress((void**)&p_wlast, g_wlast);
    cudaGetSymbolAddress((void**)&p_xnb,   g_xnb);
    cudaGetSymbolAddress((void**)&p_tA,    g_tA);
    cudaGetSymbolAddress((void**)&p_tB,    g_tB);

    // dynamic smem: 3 stages of (128 + 160) * 40 bf16
    constexpr int SMEM_G = STAGES * (BM_T + 160) * LDT * 2;  // 69120 B
    cudaFuncSetAttribute(gemm_k<160,0>, cudaFuncAttributeMaxDynamicSharedMemorySize, SMEM_G);
    cudaFuncSetAttribute(gemm_k<160,1>, cudaFuncAttributeMaxDynamicSharedMemorySize, SMEM_G);

    // 1. gate vectors
    bm_kernel<<<1, 512>>>(snr, bm_w1, bm_b1, bm_w2, bm_b2, bm_w3, bm_b3);

    // 2. fold gates into weights (bf16), fold biases
    fold_row_kernel<<<240, 256>>>(sm0_w, sm0_b, p_bm, p_w0, p_bias, HDIM, EDIM);
    for (int i = 0; i < NLAYER - 1; i++) {
        fold_row_kernel<<<240, 256>>>(smm_w + (size_t)i*HDIM*HDIM, smm_b + i*HDIM,
                                      p_bm + (i+1)*HDIM,
                                      p_wmid + (size_t)i*HDIM*HDIM, p_bias + (i+1)*HDIM,
                                      HDIM, HDIM);
    }
    conv_kernel<<<120, 256>>>(sml_w, p_wlast, EDIM*HDIM);

    // 3. LayerNorm
    ln_kernel<<<MTOK/8, 256>>>(x, norm_w, norm_b);

    // 4. GEMM chain
    // E->H
    gemm_k<160,0><<<dim3(MTOK/BM_T, HDIM/160), 256, SMEM_G>>>(
        p_xnb, p_w0, p_bias, nullptr, p_tA, MTOK, HDIM, EDIM);
    // 6x H->H (ping-pong)
    __nv_bfloat16* bufs[2] = {p_tA, p_tB};
    for (int i = 0; i < NLAYER - 1; i++) {
        gemm_k<160,0><<<dim3(MTOK/BM_T, HDIM/160), 256, SMEM_G>>>(
            bufs[i & 1], p_wmid + (size_t)i*HDIM*HDIM, p_bias + (i+1)*HDIM, nullptr,
            bufs[(i & 1) ^ 1], MTOK, HDIM, HDIM);
    }
    // H->E with fused sigmoid * xn -> fp32 xg (chain ends in g_tA after 6 mids)
    gemm_k<160,1><<<dim3(MTOK/BM_T, EDIM/160), 256, SMEM_G>>>(
        p_tA, p_wlast, sml_b, p_xnf, p_xgf, MTOK, EDIM, HDIM);
    // head E->C, fp32
    head_kernel<<<MTOK/128, 256>>>(p_xgf, head_w, head_b, (float*)d_out);
}

// round 9
// speedup vs baseline: 1.4949x; 1.4949x over previous
#include <cuda_runtime.h>
#include <cuda_bf16.h>
#include <cstdint>

// ---------------- problem constants ----------------
#define BATCH 64
#define LSEQ  1024
#define EDIM  320
#define HDIM  480
#define CDIM  32
#define NLAYER 7
#define MTOK  (BATCH*LSEQ)   // 65536

// ---------------- device scratch ----------------
__device__ float          g_bm[NLAYER*HDIM];
__device__ float          g_bias[NLAYER*HDIM];
__device__ __nv_bfloat16  g_w0[HDIM*EDIM];
__device__ __nv_bfloat16  g_wmid[(NLAYER-1)*HDIM*HDIM];
__device__ __nv_bfloat16  g_wlast[EDIM*HDIM];
__device__ float          g_xnf[(size_t)MTOK*EDIM];
__device__ __nv_bfloat16  g_xnb[(size_t)MTOK*EDIM];
__device__ __nv_bfloat16  g_tA[(size_t)MTOK*HDIM];
__device__ __nv_bfloat16  g_tB[(size_t)MTOK*HDIM];
__device__ float          g_xgf[(size_t)MTOK*EDIM];

// ---------------- small kernels ----------------

__global__ void bm_kernel(const float* __restrict__ snr,
                          const float* __restrict__ w1, const float* __restrict__ b1,
                          const float* __restrict__ w2, const float* __restrict__ b2,
                          const float* __restrict__ w3, const float* __restrict__ b3)
{
    __shared__ float h1[HDIM];
    __shared__ float h2[HDIM];
    const int j = threadIdx.x;
    const float s = snr[0];
    for (int i = 0; i < NLAYER; i++) {
        if (j < HDIM)
            h1[j] = fmaxf(0.f, s * w1[i*HDIM + j] + b1[i*HDIM + j]);
        __syncthreads();
        if (j < HDIM) {
            const float* wp = w2 + ((size_t)i*HDIM + j) * HDIM;
            float acc = b2[i*HDIM + j];
            for (int k = 0; k < HDIM; k++) acc += wp[k] * h1[k];
            h2[j] = fmaxf(0.f, acc);
        }
        __syncthreads();
        if (j < HDIM) {
            const float* wp = w3 + ((size_t)i*HDIM + j) * HDIM;
            float acc = b3[i*HDIM + j];
            for (int k = 0; k < HDIM; k++) acc += wp[k] * h2[k];
            g_bm[i*HDIM + j] = 1.f / (1.f + expf(-acc));
        }
        __syncthreads();
    }
}

// One launch: fold ALL gate vectors into all sm weights + biases (bf16 out).
__global__ void fold_all_kernel(const float* __restrict__ sm0_w, const float* __restrict__ sm0_b,
                                const float* __restrict__ smm_w, const float* __restrict__ smm_b)
{
    const int stride = gridDim.x * blockDim.x;
    const int g = blockIdx.x * blockDim.x + threadIdx.x;
    const int N0 = HDIM * EDIM;
    const int NM = HDIM * HDIM;
    const int TOT = N0 + (NLAYER - 1) * NM;
    for (int idx = g; idx < TOT; idx += stride) {
        if (idx < N0) {
            const int r = idx / EDIM;
            g_w0[idx] = __float2bfloat16(sm0_w[idx] * g_bm[r]);
        } else {
            const int j = idx - N0;
            const int i = j / NM;
            const int r = (j - i * NM) / HDIM;
            g_wmid[j] = __float2bfloat16(smm_w[j] * g_bm[(i + 1) * HDIM + r]);
        }
    }
    for (int idx = g; idx < NLAYER * HDIM; idx += stride) {
        const int i = idx / HDIM;
        const int r = idx - i * HDIM;
        const float b = (i == 0) ? sm0_b[r] : smm_b[(i - 1) * HDIM + r];
        g_bias[idx] = b * g_bm[idx];
    }
}

__global__ void conv_kernel(const float* __restrict__ w, __nv_bfloat16* __restrict__ wo, int n)
{
    const int stride = gridDim.x * blockDim.x;
    for (int idx = blockIdx.x * blockDim.x + threadIdx.x; idx < n; idx += stride)
        wo[idx] = __float2bfloat16(w[idx]);
}

__global__ void ln_kernel(const float* __restrict__ x,
                          const float* __restrict__ w, const float* __restrict__ b)
{
    const int warp = threadIdx.x >> 5;
    const int lane = threadIdx.x & 31;
    const size_t t = (size_t)blockIdx.x * 8 + warp;
    const float* xp = x + t * EDIM;
    float v[10];
    float s = 0.f, s2 = 0.f;
    #pragma unroll
    for (int i = 0; i < 10; i++) {
        v[i] = xp[lane + 32*i];
        s  += v[i];
        s2 += v[i]*v[i];
    }
    #pragma unroll
    for (int o = 16; o > 0; o >>= 1) {
        s  += __shfl_xor_sync(0xffffffffu, s,  o);
        s2 += __shfl_xor_sync(0xffffffffu, s2, o);
    }
    const float mu  = s  * (1.f/EDIM);
    const float var = s2 * (1.f/EDIM) - mu*mu;
    const float inv = 1.f / sqrtf(var + 1e-5f);
    #pragma unroll
    for (int i = 0; i < 10; i++) {
        const int c = lane + 32*i;
        const float y = (v[i] - mu) * inv * w[c] + b[c];
        g_xnf[t*EDIM + c] = y;
        g_xnb[t*EDIM + c] = __float2bfloat16(y);
    }
}

// ---------------- GEMM: C[M,N] = A[M,K] @ W[N,K]^T + bias, mma.sync bf16 ----------------
// 512 threads, 16 warps as 4(M) x 4(N). BM=128, BN=160, BK=32, 4-stage cp.async ring.
#define BM_T 128
#define BK_T 32
#define LDT  (BK_T + 8)
#define STAGES 4

__device__ __forceinline__ void cp16(uint32_t s, const void* g) {
    asm volatile("cp.async.cg.shared.global [%0], [%1], 16;" :: "r"(s), "l"(g));
}
__device__ __forceinline__ void ldm4(uint32_t a, uint32_t& r0, uint32_t& r1, uint32_t& r2, uint32_t& r3) {
    asm volatile("ldmatrix.sync.aligned.m8n8.x4.shared.b16 {%0,%1,%2,%3}, [%4];"
                 : "=r"(r0), "=r"(r1), "=r"(r2), "=r"(r3) : "r"(a));
}
__device__ __forceinline__ void ldm2(uint32_t a, uint32_t& r0, uint32_t& r1) {
    asm volatile("ldmatrix.sync.aligned.m8n8.x2.shared.b16 {%0,%1}, [%2];"
                 : "=r"(r0), "=r"(r1) : "r"(a));
}
__device__ __forceinline__ void mma16816(float* c, const uint32_t* a, const uint32_t* b) {
    asm volatile("mma.sync.aligned.m16n8k16.row.col.f32.bf16.bf16.f32 "
                 "{%0,%1,%2,%3}, {%4,%5,%6,%7}, {%8,%9}, {%0,%1,%2,%3};"
                 : "+f"(c[0]), "+f"(c[1]), "+f"(c[2]), "+f"(c[3])
                 : "r"(a[0]), "r"(a[1]), "r"(a[2]), "r"(a[3]), "r"(b[0]), "r"(b[1]));
}

// EPI: 0 = bias -> bf16 ; 1 = sigmoid(.+bias)*xn -> fp32
template<int BN, int EPI>
__global__ __launch_bounds__(512, 1) void gemm_k(
    const __nv_bfloat16* __restrict__ A, const __nv_bfloat16* __restrict__ W,
    const float* __restrict__ bias, const float* __restrict__ xnf,
    void* __restrict__ Cout, int M, int N, int K)
{
    constexpr int NIW  = BN / 32;         // n8 tiles per warp (warp covers BN/4 cols) = 5
    constexpr int ASTG = BM_T * LDT;
    constexpr int BSTG = BN * LDT;

    extern __shared__ __align__(16) __nv_bfloat16 smem[];
    __nv_bfloat16* Asm = smem;
    __nv_bfloat16* Bsm = smem + STAGES * ASTG;

    const int tid  = threadIdx.x;
    const int lane = tid & 31;
    const int warp = tid >> 5;
    const int wr = warp & 3;    // 4 warps along M: 32 rows each
    const int wc = warp >> 2;   // 4 warps along N: BN/4 cols each

    const uint32_t sA = (uint32_t)__cvta_generic_to_shared(Asm);
    const uint32_t sB = (uint32_t)__cvta_generic_to_shared(Bsm);
    const size_t Arow0 = (size_t)blockIdx.x * BM_T;
    const size_t Brow0 = (size_t)blockIdx.y * BN;
    const int KT = K / BK_T;

    auto load_st = [&](int kt, int buf) {
        const __nv_bfloat16* Ag = A + Arow0 * K + (size_t)kt * BK_T;
        const uint32_t sa = sA + buf * (ASTG * 2);
        for (int id = tid; id < BM_T * 4; id += 512) {
            const int r = id >> 2, c = (id & 3) * 8;
            cp16(sa + (r * LDT + c) * 2, Ag + (size_t)r * K + c);
        }
        const __nv_bfloat16* Bg = W + Brow0 * K + (size_t)kt * BK_T;
        const uint32_t sb = sB + buf * (BSTG * 2);
        for (int id = tid; id < BN * 4; id += 512) {
            const int r = id >> 2, c = (id & 3) * 8;
            cp16(sb + (r * LDT + c) * 2, Bg + (size_t)r * K + c);
        }
        asm volatile("cp.async.commit_group;");
    };

    float acc[2][NIW][4];
    #pragma unroll
    for (int mi = 0; mi < 2; mi++)
        #pragma unroll
        for (int ni = 0; ni < NIW; ni++)
            #pragma unroll
            for (int e = 0; e < 4; e++) acc[mi][ni][e] = 0.f;

    // prologue: 3 stages in flight
    load_st(0, 0);
    load_st(1, 1);
    load_st(2, 2);

    for (int kt = 0; kt < KT; kt++) {
        const int rem = KT - 1 - kt;
        if (rem >= 2)      asm volatile("cp.async.wait_group 2;");
        else if (rem == 1) asm volatile("cp.async.wait_group 1;");
        else               asm volatile("cp.async.wait_group 0;");
        __syncthreads();

        if (kt + 3 < KT) load_st(kt + 3, (kt + 3) & 3);

        const int buf = kt & 3;
        const uint32_t baseA = sA + buf * (ASTG * 2);
        const uint32_t baseB = sB + buf * (BSTG * 2);
        #pragma unroll
        for (int ks = 0; ks < 2; ks++) {
            uint32_t af[2][4];
            #pragma unroll
            for (int mi = 0; mi < 2; mi++) {
                const int row = wr * 32 + mi * 16 + (lane & 15);
                const int col = ks * 16 + (lane >> 4) * 8;
                ldm4(baseA + (row * LDT + col) * 2, af[mi][0], af[mi][1], af[mi][2], af[mi][3]);
            }
            uint32_t bf[NIW][2];
            #pragma unroll
            for (int np = 0; np < NIW / 2; np++) {
                const int row = wc * (BN / 4) + np * 16 + (lane & 7) + ((lane >> 4) << 3);
                const int col = ks * 16 + (((lane >> 3) & 1) << 3);
                ldm4(baseB + (row * LDT + col) * 2,
                     bf[2*np][0], bf[2*np][1], bf[2*np+1][0], bf[2*np+1][1]);
            }
            if (NIW & 1) {
                const int l = lane & 15;
                const int row = wc * (BN / 4) + (NIW - 1) * 8 + (l & 7);
                const int col = ks * 16 + ((l >> 3) << 3);
                ldm2(baseB + (row * LDT + col) * 2, bf[NIW-1][0], bf[NIW-1][1]);
            }
            #pragma unroll
            for (int mi = 0; mi < 2; mi++)
                #pragma unroll
                for (int ni = 0; ni < NIW; ni++)
                    mma16816(acc[mi][ni], af[mi], bf[ni]);
        }
    }

    // epilogue
    const size_t mb = Arow0 + wr * 32;
    const int nb = (int)Brow0 + wc * (BN / 4);
    #pragma unroll
    for (int mi = 0; mi < 2; mi++) {
        #pragma unroll
        for (int ni = 0; ni < NIW; ni++) {
            const size_t m0 = mb + mi * 16 + (lane >> 2);
            const int n0 = nb + ni * 8 + (lane & 3) * 2;
            #pragma unroll
            for (int e = 0; e < 4; e++) {
                const size_t m = m0 + ((e >= 2) ? 8 : 0);
                const int n = n0 + (e & 1);
                const float v = acc[mi][ni][e] + bias[n];
                if (EPI == 0) {
                    ((__nv_bfloat16*)Cout)[m * N + n] = __float2bfloat16(v);
                } else {
                    const float sg = 1.f / (1.f + __expf(-v));
                    ((float*)Cout)[m * N + n] = sg * xnf[m * N + n];
                }
            }
        }
    }
}

// ---------------- head GEMM: fp32, M=65536 N=32 K=320 ----------------
__global__ __launch_bounds__(256, 2) void head_kernel(
    const float* __restrict__ A, const float* __restrict__ W,
    const float* __restrict__ bias, float* __restrict__ out)
{
    __shared__ float ws[EDIM * CDIM];
    __shared__ float as[32 * 128];

    const int tid = threadIdx.x;
    for (int i = tid; i < EDIM * CDIM; i += 256) {
        const int c = i & 31;
        const int k = i >> 5;
        ws[k * CDIM + c] = W[c * EDIM + k];
    }

    const size_t row0 = (size_t)blockIdx.x * 128;
    const int rg = tid >> 3;
    const int cg = tid & 7;

    float acc[4][4];
    #pragma unroll
    for (int i = 0; i < 4; i++)
        #pragma unroll
        for (int j = 0; j < 4; j++) acc[i][j] = 0.f;

    for (int k0 = 0; k0 < EDIM; k0 += 32) {
        __syncthreads();
        #pragma unroll
        for (int i = 0; i < 4; i++) {
            const int idx = tid + 256 * i;
            const int r  = idx & 127;
            const int kq = idx >> 7;
            const float4 v = *(const float4*)(A + (row0 + r) * EDIM + k0 + kq * 4);
            as[(kq * 4 + 0) * 128 + r] = v.x;
            as[(kq * 4 + 1) * 128 + r] = v.y;
            as[(kq * 4 + 2) * 128 + r] = v.z;
            as[(kq * 4 + 3) * 128 + r] = v.w;
        }
        __syncthreads();
        #pragma unroll
        for (int k = 0; k < 32; k++) {
            const float4 av = *(const float4*)(as + k * 128 + rg * 4);
            const float4 bv = *(const float4*)(ws + (k0 + k) * CDIM + cg * 4);
            acc[0][0] += av.x * bv.x; acc[0][1] += av.x * bv.y;
            acc[0][2] += av.x * bv.z; acc[0][3] += av.x * bv.w;
            acc[1][0] += av.y * bv.x; acc[1][1] += av.y * bv.y;
            acc[1][2] += av.y * bv.z; acc[1][3] += av.y * bv.w;
            acc[2][0] += av.z * bv.x; acc[2][1] += av.z * bv.y;
            acc[2][2] += av.z * bv.z; acc[2][3] += av.z * bv.w;
            acc[3][0] += av.w * bv.x; acc[3][1] += av.w * bv.y;
            acc[3][2] += av.w * bv.z; acc[3][3] += av.w * bv.w;
        }
    }

    const float4 bv = *(const float4*)(bias + cg * 4);
    #pragma unroll
    for (int i = 0; i < 4; i++) {
        float4 o;
        o.x = acc[i][0] + bv.x;
        o.y = acc[i][1] + bv.y;
        o.z = acc[i][2] + bv.z;
        o.w = acc[i][3] + bv.w;
        *(float4*)(out + (row0 + rg * 4 + i) * CDIM + cg * 4) = o;
    }
}

// ---------------- launch ----------------
extern "C" void kernel_launch(void* const* d_in, const int* in_sizes, int n_in,
                              void* d_out, int out_size)
{
    (void)in_sizes; (void)n_in; (void)out_size;
    const float* x       = (const float*)d_in[0];
    const float* snr     = (const float*)d_in[1];
    const float* norm_w  = (const float*)d_in[2];
    const float* norm_b  = (const float*)d_in[3];
    const float* sm0_w   = (const float*)d_in[4];
    const float* sm0_b   = (const float*)d_in[5];
    const float* smm_w   = (const float*)d_in[6];
    const float* smm_b   = (const float*)d_in[7];
    const float* sml_w   = (const float*)d_in[8];
    const float* sml_b   = (const float*)d_in[9];
    const float* bm_w1   = (const float*)d_in[10];
    const float* bm_b1   = (const float*)d_in[11];
    const float* bm_w2   = (const float*)d_in[12];
    const float* bm_b2   = (const float*)d_in[13];
    const float* bm_w3   = (const float*)d_in[14];
    const float* bm_b3   = (const float*)d_in[15];
    const float* head_w  = (const float*)d_in[16];
    const float* head_b  = (const float*)d_in[17];

    float *p_bias, *p_xnf, *p_xgf;
    __nv_bfloat16 *p_w0, *p_wmid, *p_wlast, *p_xnb, *p_tA, *p_tB;
    cudaGetSymbolAddress((void**)&p_bias,  g_bias);
    cudaGetSymbolAddress((void**)&p_xnf,   g_xnf);
    cudaGetSymbolAddress((void**)&p_xgf,   g_xgf);
    cudaGetSymbolAddress((void**)&p_w0,    g_w0);
    cudaGetSymbolAddress((void**)&p_wmid,  g_wmid);
    cudaGetSymbolAddress((void**)&p_wlast, g_wlast);
    cudaGetSymbolAddress((void**)&p_xnb,   g_xnb);
    cudaGetSymbolAddress((void**)&p_tA,    g_tA);
    cudaGetSymbolAddress((void**)&p_tB,    g_tB);

    // dynamic smem: 4 stages of (128 + 160) * 40 bf16 = 92160 B
    constexpr int SMEM_G = STAGES * (BM_T + 160) * LDT * 2;
    cudaFuncSetAttribute(gemm_k<160,0>, cudaFuncAttributeMaxDynamicSharedMemorySize, SMEM_G);
    cudaFuncSetAttribute(gemm_k<160,1>, cudaFuncAttributeMaxDynamicSharedMemorySize, SMEM_G);

    // launches: bm(0), fold_all(1), conv(2), ln(3), gemm0(4), gemm1(5) <- ncu -s 5 profiles a mid GEMM
    bm_kernel<<<1, 512>>>(snr, bm_w1, bm_b1, bm_w2, bm_b2, bm_w3, bm_b3);
    fold_all_kernel<<<480, 256>>>(sm0_w, sm0_b, smm_w, smm_b);
    conv_kernel<<<120, 256>>>(sml_w, p_wlast, EDIM*HDIM);
    ln_kernel<<<MTOK/8, 256>>>(x, norm_w, norm_b);

    // E->H
    gemm_k<160,0><<<dim3(MTOK/BM_T, HDIM/160), 512, SMEM_G>>>(
        p_xnb, p_w0, p_bias, nullptr, p_tA, MTOK, HDIM, EDIM);
    // 6x H->H (ping-pong)
    __nv_bfloat16* bufs[2] = {p_tA, p_tB};
    for (int i = 0; i < NLAYER - 1; i++) {
        gemm_k<160,0><<<dim3(MTOK/BM_T, HDIM/160), 512, SMEM_G>>>(
            bufs[i & 1], p_wmid + (size_t)i*HDIM*HDIM, p_bias + (i+1)*HDIM, nullptr,
            bufs[(i & 1) ^ 1], MTOK, HDIM, HDIM);
    }
    // H->E with fused sigmoid * xn -> fp32 xg (chain ends in g_tA after 6 mids)
    gemm_k<160,1><<<dim3(MTOK/BM_T, EDIM/160), 512, SMEM_G>>>(
        p_tA, p_wlast, sml_b, p_xnf, p_xgf, MTOK, EDIM, HDIM);
    // head E->C, fp32
    head_kernel<<<MTOK/128, 256>>>(p_xgf, head_w, head_b, (float*)d_out);
}

// round 10
// speedup vs baseline: 1.5823x; 1.0585x over previous
#include <cuda_runtime.h>
#include <cuda_bf16.h>
#include <cstdint>

// ---------------- problem constants ----------------
#define BATCH 64
#define LSEQ  1024
#define EDIM  320
#define HDIM  480
#define CDIM  32
#define NLAYER 7
#define MTOK  (BATCH*LSEQ)   // 65536

// ---------------- device scratch ----------------
__device__ float          g_bm[NLAYER*HDIM];
__device__ float          g_Ma[HDIM*EDIM];     // composite ping
__device__ float          g_Mb[HDIM*EDIM];     // composite pong
__device__ float          g_cva[HDIM];
__device__ float          g_cvb[HDIM];
__device__ float          g_Wt[EDIM*EDIM];     // final composite weight (fp32)
__device__ float          g_ct[EDIM];          // final composite bias
__device__ __nv_bfloat16  g_wtb[EDIM*EDIM];    // bf16 copy for tensor-core GEMM
__device__ float          g_xnf[(size_t)MTOK*EDIM];
__device__ __nv_bfloat16  g_xnb[(size_t)MTOK*EDIM];
__device__ float          g_xgf[(size_t)MTOK*EDIM];

// ---------------- small kernels ----------------

// Adaptive modulator: snr scalar -> 7 gate vectors of H. Single block.
__global__ void bm_kernel(const float* __restrict__ snr,
                          const float* __restrict__ w1, const float* __restrict__ b1,
                          const float* __restrict__ w2, const float* __restrict__ b2,
                          const float* __restrict__ w3, const float* __restrict__ b3)
{
    __shared__ float h1[HDIM];
    __shared__ float h2[HDIM];
    const int j = threadIdx.x;
    const float s = snr[0];
    for (int i = 0; i < NLAYER; i++) {
        if (j < HDIM)
            h1[j] = fmaxf(0.f, s * w1[i*HDIM + j] + b1[i*HDIM + j]);
        __syncthreads();
        if (j < HDIM) {
            const float* wp = w2 + ((size_t)i*HDIM + j) * HDIM;
            float acc = b2[i*HDIM + j];
            for (int k = 0; k < HDIM; k++) acc += wp[k] * h1[k];
            h2[j] = fmaxf(0.f, acc);
        }
        __syncthreads();
        if (j < HDIM) {
            const float* wp = w3 + ((size_t)i*HDIM + j) * HDIM;
            float acc = b3[i*HDIM + j];
            for (int k = 0; k < HDIM; k++) acc += wp[k] * h2[k];
            g_bm[i*HDIM + j] = 1.f / (1.f + expf(-acc));
        }
        __syncthreads();
    }
}

// M0 = diag(bm0) * sm0_w ; c0 = bm0 * sm0_b
__global__ void diag0_kernel(const float* __restrict__ w, const float* __restrict__ b,
                             float* __restrict__ M0, float* __restrict__ c0)
{
    const int idx = blockIdx.x * blockDim.x + threadIdx.x;
    const int stride = gridDim.x * blockDim.x;
    for (int i = idx; i < HDIM*EDIM; i += stride) {
        const int r = i / EDIM;
        M0[i] = g_bm[r] * w[i];
    }
    if (idx < HDIM) c0[idx] = g_bm[idx] * b[idx];
}

// C[M,N] = diag(rs) * (A[M,K] @ B[K,N]) ; fp32 row-major, rs may be null.
// Block 256 threads = 16x16, tile 32x32 (each thread 2x2), TILE_K=32.
__global__ __launch_bounds__(256) void mm_f32(
    const float* __restrict__ A, const float* __restrict__ B,
    const float* __restrict__ rs, float* __restrict__ C,
    int M, int N, int K)
{
    __shared__ float As[32][33];
    __shared__ float Bs[32][33];
    const int tid = threadIdx.x;
    const int tx = tid & 15, ty = tid >> 4;
    const int r0 = blockIdx.y * 32, c0 = blockIdx.x * 32;

    float acc00 = 0.f, acc01 = 0.f, acc10 = 0.f, acc11 = 0.f;
    for (int k0 = 0; k0 < K; k0 += 32) {
        for (int i = tid; i < 1024; i += 256) {
            const int r = i >> 5, c = i & 31;
            As[r][c] = A[(size_t)(r0 + r) * K + k0 + c];
            Bs[r][c] = B[(size_t)(k0 + r) * N + c0 + c];
        }
        __syncthreads();
        #pragma unroll
        for (int k = 0; k < 32; k++) {
            const float a0 = As[ty*2][k],   a1 = As[ty*2+1][k];
            const float b0 = Bs[k][tx*2],   b1 = Bs[k][tx*2+1];
            acc00 += a0*b0; acc01 += a0*b1;
            acc10 += a1*b0; acc11 += a1*b1;
        }
        __syncthreads();
    }
    const float s0 = rs ? rs[r0 + ty*2]     : 1.f;
    const float s1 = rs ? rs[r0 + ty*2 + 1] : 1.f;
    C[(size_t)(r0 + ty*2)   * N + c0 + tx*2]     = s0 * acc00;
    C[(size_t)(r0 + ty*2)   * N + c0 + tx*2 + 1] = s0 * acc01;
    C[(size_t)(r0 + ty*2+1) * N + c0 + tx*2]     = s1 * acc10;
    C[(size_t)(r0 + ty*2+1) * N + c0 + tx*2 + 1] = s1 * acc11;
}

// vout = (bm ? diag(bm) : I) * (W @ vin + b) ; W[M,K] row-major
__global__ void mv_f32(const float* __restrict__ W, const float* __restrict__ vin,
                       const float* __restrict__ b, const float* __restrict__ bm,
                       float* __restrict__ vout, int M, int K)
{
    const int r = blockIdx.x * blockDim.x + threadIdx.x;
    if (r < M) {
        const float* w = W + (size_t)r * K;
        float acc = 0.f;
        for (int k = 0; k < K; k++) acc += w[k] * vin[k];
        acc += b[r];
        vout[r] = bm ? bm[r] * acc : acc;
    }
}

__global__ void conv_kernel(const float* __restrict__ w, __nv_bfloat16* __restrict__ wo, int n)
{
    const int stride = gridDim.x * blockDim.x;
    for (int idx = blockIdx.x * blockDim.x + threadIdx.x; idx < n; idx += stride)
        wo[idx] = __float2bfloat16(w[idx]);
}

// LayerNorm: one warp per token (E=320 = 32*10). fp32 + bf16 copies.
__global__ void ln_kernel(const float* __restrict__ x,
                          const float* __restrict__ w, const float* __restrict__ b)
{
    const int warp = threadIdx.x >> 5;
    const int lane = threadIdx.x & 31;
    const size_t t = (size_t)blockIdx.x * 8 + warp;
    const float* xp = x + t * EDIM;
    float v[10];
    float s = 0.f, s2 = 0.f;
    #pragma unroll
    for (int i = 0; i < 10; i++) {
        v[i] = xp[lane + 32*i];
        s  += v[i];
        s2 += v[i]*v[i];
    }
    #pragma unroll
    for (int o = 16; o > 0; o >>= 1) {
        s  += __shfl_xor_sync(0xffffffffu, s,  o);
        s2 += __shfl_xor_sync(0xffffffffu, s2, o);
    }
    const float mu  = s  * (1.f/EDIM);
    const float var = s2 * (1.f/EDIM) - mu*mu;
    const float inv = 1.f / sqrtf(var + 1e-5f);
    #pragma unroll
    for (int i = 0; i < 10; i++) {
        const int c = lane + 32*i;
        const float y = (v[i] - mu) * inv * w[c] + b[c];
        g_xnf[t*EDIM + c] = y;
        g_xnb[t*EDIM + c] = __float2bfloat16(y);
    }
}

// ---------------- GEMM: C[M,N] = A[M,K] @ W[N,K]^T + bias, mma.sync bf16 ----------------
// 512 threads, 16 warps as 4(M) x 4(N). BM=128, BN=160, BK=32, 4-stage cp.async ring.
#define BM_T 128
#define BK_T 32
#define LDT  (BK_T + 8)
#define STAGES 4

__device__ __forceinline__ void cp16(uint32_t s, const void* g) {
    asm volatile("cp.async.cg.shared.global [%0], [%1], 16;" :: "r"(s), "l"(g));
}
__device__ __forceinline__ void ldm4(uint32_t a, uint32_t& r0, uint32_t& r1, uint32_t& r2, uint32_t& r3) {
    asm volatile("ldmatrix.sync.aligned.m8n8.x4.shared.b16 {%0,%1,%2,%3}, [%4];"
                 : "=r"(r0), "=r"(r1), "=r"(r2), "=r"(r3) : "r"(a));
}
__device__ __forceinline__ void ldm2(uint32_t a, uint32_t& r0, uint32_t& r1) {
    asm volatile("ldmatrix.sync.aligned.m8n8.x2.shared.b16 {%0,%1}, [%2];"
                 : "=r"(r0), "=r"(r1) : "r"(a));
}
__device__ __forceinline__ void mma16816(float* c, const uint32_t* a, const uint32_t* b) {
    asm volatile("mma.sync.aligned.m16n8k16.row.col.f32.bf16.bf16.f32 "
                 "{%0,%1,%2,%3}, {%4,%5,%6,%7}, {%8,%9}, {%0,%1,%2,%3};"
                 : "+f"(c[0]), "+f"(c[1]), "+f"(c[2]), "+f"(c[3])
                 : "r"(a[0]), "r"(a[1]), "r"(a[2]), "r"(a[3]), "r"(b[0]), "r"(b[1]));
}

// EPI: 0 = bias -> bf16 ; 1 = sigmoid(.+bias)*xn -> fp32
template<int BN, int EPI>
__global__ __launch_bounds__(512, 1) void gemm_k(
    const __nv_bfloat16* __restrict__ A, const __nv_bfloat16* __restrict__ W,
    const float* __restrict__ bias, const float* __restrict__ xnf,
    void* __restrict__ Cout, int M, int N, int K)
{
    constexpr int NIW  = BN / 32;
    constexpr int ASTG = BM_T * LDT;
    constexpr int BSTG = BN * LDT;

    extern __shared__ __align__(16) __nv_bfloat16 smem[];
    __nv_bfloat16* Asm = smem;
    __nv_bfloat16* Bsm = smem + STAGES * ASTG;

    const int tid  = threadIdx.x;
    const int lane = tid & 31;
    const int warp = tid >> 5;
    const int wr = warp & 3;
    const int wc = warp >> 2;

    const uint32_t sA = (uint32_t)__cvta_generic_to_shared(Asm);
    const uint32_t sB = (uint32_t)__cvta_generic_to_shared(Bsm);
    const size_t Arow0 = (size_t)blockIdx.x * BM_T;
    const size_t Brow0 = (size_t)blockIdx.y * BN;
    const int KT = K / BK_T;

    auto load_st = [&](int kt, int buf) {
        const __nv_bfloat16* Ag = A + Arow0 * K + (size_t)kt * BK_T;
        const uint32_t sa = sA + buf * (ASTG * 2);
        for (int id = tid; id < BM_T * 4; id += 512) {
            const int r = id >> 2, c = (id & 3) * 8;
            cp16(sa + (r * LDT + c) * 2, Ag + (size_t)r * K + c);
        }
        const __nv_bfloat16* Bg = W + Brow0 * K + (size_t)kt * BK_T;
        const uint32_t sb = sB + buf * (BSTG * 2);
        for (int id = tid; id < BN * 4; id += 512) {
            const int r = id >> 2, c = (id & 3) * 8;
            cp16(sb + (r * LDT + c) * 2, Bg + (size_t)r * K + c);
        }
        asm volatile("cp.async.commit_group;");
    };

    float acc[2][NIW][4];
    #pragma unroll
    for (int mi = 0; mi < 2; mi++)
        #pragma unroll
        for (int ni = 0; ni < NIW; ni++)
            #pragma unroll
            for (int e = 0; e < 4; e++) acc[mi][ni][e] = 0.f;

    load_st(0, 0);
    load_st(1, 1);
    load_st(2, 2);

    for (int kt = 0; kt < KT; kt++) {
        const int rem = KT - 1 - kt;
        if (rem >= 2)      asm volatile("cp.async.wait_group 2;");
        else if (rem == 1) asm volatile("cp.async.wait_group 1;");
        else               asm volatile("cp.async.wait_group 0;");
        __syncthreads();

        if (kt + 3 < KT) load_st(kt + 3, (kt + 3) & 3);

        const int buf = kt & 3;
        const uint32_t baseA = sA + buf * (ASTG * 2);
        const uint32_t baseB = sB + buf * (BSTG * 2);
        #pragma unroll
        for (int ks = 0; ks < 2; ks++) {
            uint32_t af[2][4];
            #pragma unroll
            for (int mi = 0; mi < 2; mi++) {
                const int row = wr * 32 + mi * 16 + (lane & 15);
                const int col = ks * 16 + (lane >> 4) * 8;
                ldm4(baseA + (row * LDT + col) * 2, af[mi][0], af[mi][1], af[mi][2], af[mi][3]);
            }
            uint32_t bf[NIW][2];
            #pragma unroll
            for (int np = 0; np < NIW / 2; np++) {
                const int row = wc * (BN / 4) + np * 16 + (lane & 7) + ((lane >> 4) << 3);
                const int col = ks * 16 + (((lane >> 3) & 1) << 3);
                ldm4(baseB + (row * LDT + col) * 2,
                     bf[2*np][0], bf[2*np][1], bf[2*np+1][0], bf[2*np+1][1]);
            }
            if (NIW & 1) {
                const int l = lane & 15;
                const int row = wc * (BN / 4) + (NIW - 1) * 8 + (l & 7);
                const int col = ks * 16 + ((l >> 3) << 3);
                ldm2(baseB + (row * LDT + col) * 2, bf[NIW-1][0], bf[NIW-1][1]);
            }
            #pragma unroll
            for (int mi = 0; mi < 2; mi++)
                #pragma unroll
                for (int ni = 0; ni < NIW; ni++)
                    mma16816(acc[mi][ni], af[mi], bf[ni]);
        }
    }

    const size_t mb = Arow0 + wr * 32;
    const int nb = (int)Brow0 + wc * (BN / 4);
    #pragma unroll
    for (int mi = 0; mi < 2; mi++) {
        #pragma unroll
        for (int ni = 0; ni < NIW; ni++) {
            const size_t m0 = mb + mi * 16 + (lane >> 2);
            const int n0 = nb + ni * 8 + (lane & 3) * 2;
            #pragma unroll
            for (int e = 0; e < 4; e++) {
                const size_t m = m0 + ((e >= 2) ? 8 : 0);
                const int n = n0 + (e & 1);
                const float v = acc[mi][ni][e] + bias[n];
                if (EPI == 0) {
                    ((__nv_bfloat16*)Cout)[m * N + n] = __float2bfloat16(v);
                } else {
                    const float sg = 1.f / (1.f + __expf(-v));
                    ((float*)Cout)[m * N + n] = sg * xnf[m * N + n];
                }
            }
        }
    }
}

// ---------------- head GEMM: fp32, M=65536 N=32 K=320 ----------------
__global__ __launch_bounds__(256, 2) void head_kernel(
    const float* __restrict__ A, const float* __restrict__ W,
    const float* __restrict__ bias, float* __restrict__ out)
{
    __shared__ float ws[EDIM * CDIM];
    __shared__ float as[32 * 128];

    const int tid = threadIdx.x;
    for (int i = tid; i < EDIM * CDIM; i += 256) {
        const int c = i & 31;
        const int k = i >> 5;
        ws[k * CDIM + c] = W[c * EDIM + k];
    }

    const size_t row0 = (size_t)blockIdx.x * 128;
    const int rg = tid >> 3;
    const int cg = tid & 7;

    float acc[4][4];
    #pragma unroll
    for (int i = 0; i < 4; i++)
        #pragma unroll
        for (int j = 0; j < 4; j++) acc[i][j] = 0.f;

    for (int k0 = 0; k0 < EDIM; k0 += 32) {
        __syncthreads();
        #pragma unroll
        for (int i = 0; i < 4; i++) {
            const int idx = tid + 256 * i;
            const int r  = idx & 127;
            const int kq = idx >> 7;
            const float4 v = *(const float4*)(A + (row0 + r) * EDIM + k0 + kq * 4);
            as[(kq * 4 + 0) * 128 + r] = v.x;
            as[(kq * 4 + 1) * 128 + r] = v.y;
            as[(kq * 4 + 2) * 128 + r] = v.z;
            as[(kq * 4 + 3) * 128 + r] = v.w;
        }
        __syncthreads();
        #pragma unroll
        for (int k = 0; k < 32; k++) {
            const float4 av = *(const float4*)(as + k * 128 + rg * 4);
            const float4 bv = *(const float4*)(ws + (k0 + k) * CDIM + cg * 4);
            acc[0][0] += av.x * bv.x; acc[0][1] += av.x * bv.y;
            acc[0][2] += av.x * bv.z; acc[0][3] += av.x * bv.w;
            acc[1][0] += av.y * bv.x; acc[1][1] += av.y * bv.y;
            acc[1][2] += av.y * bv.z; acc[1][3] += av.y * bv.w;
            acc[2][0] += av.z * bv.x; acc[2][1] += av.z * bv.y;
            acc[2][2] += av.z * bv.z; acc[2][3] += av.z * bv.w;
            acc[3][0] += av.w * bv.x; acc[3][1] += av.w * bv.y;
            acc[3][2] += av.w * bv.z; acc[3][3] += av.w * bv.w;
        }
    }

    const float4 bv = *(const float4*)(bias + cg * 4);
    #pragma unroll
    for (int i = 0; i < 4; i++) {
        float4 o;
        o.x = acc[i][0] + bv.x;
        o.y = acc[i][1] + bv.y;
        o.z = acc[i][2] + bv.z;
        o.w = acc[i][3] + bv.w;
        *(float4*)(out + (row0 + rg * 4 + i) * CDIM + cg * 4) = o;
    }
}

// ---------------- launch ----------------
extern "C" void kernel_launch(void* const* d_in, const int* in_sizes, int n_in,
                              void* d_out, int out_size)
{
    (void)in_sizes; (void)n_in; (void)out_size;
    const float* x       = (const float*)d_in[0];
    const float* snr     = (const float*)d_in[1];
    const float* norm_w  = (const float*)d_in[2];
    const float* norm_b  = (const float*)d_in[3];
    const float* sm0_w   = (const float*)d_in[4];
    const float* sm0_b   = (const float*)d_in[5];
    const float* smm_w   = (const float*)d_in[6];
    const float* smm_b   = (const float*)d_in[7];
    const float* sml_w   = (const float*)d_in[8];
    const float* sml_b   = (const float*)d_in[9];
    const float* bm_w1   = (const float*)d_in[10];
    const float* bm_b1   = (const float*)d_in[11];
    const float* bm_w2   = (const float*)d_in[12];
    const float* bm_b2   = (const float*)d_in[13];
    const float* bm_w3   = (const float*)d_in[14];
    const float* bm_b3   = (const float*)d_in[15];
    const float* head_w  = (const float*)d_in[16];
    const float* head_b  = (const float*)d_in[17];

    float *p_bm, *p_Ma, *p_Mb, *p_cva, *p_cvb, *p_Wt, *p_ct, *p_xnf, *p_xgf;
    __nv_bfloat16 *p_wtb, *p_xnb;
    cudaGetSymbolAddress((void**)&p_bm,  g_bm);
    cudaGetSymbolAddress((void**)&p_Ma,  g_Ma);
    cudaGetSymbolAddress((void**)&p_Mb,  g_Mb);
    cudaGetSymbolAddress((void**)&p_cva, g_cva);
    cudaGetSymbolAddress((void**)&p_cvb, g_cvb);
    cudaGetSymbolAddress((void**)&p_Wt,  g_Wt);
    cudaGetSymbolAddress((void**)&p_ct,  g_ct);
    cudaGetSymbolAddress((void**)&p_wtb, g_wtb);
    cudaGetSymbolAddress((void**)&p_xnf, g_xnf);
    cudaGetSymbolAddress((void**)&p_xnb, g_xnb);
    cudaGetSymbolAddress((void**)&p_xgf, g_xgf);

    constexpr int SMEM_G = STAGES * (BM_T + 160) * LDT * 2;  // 92160 B
    cudaFuncSetAttribute(gemm_k<160,1>, cudaFuncAttributeMaxDynamicSharedMemorySize, SMEM_G);

    // ---- token-independent precompute (tiny) ----
    bm_kernel<<<1, 512>>>(snr, bm_w1, bm_b1, bm_w2, bm_b2, bm_w3, bm_b3);
    diag0_kernel<<<240, 256>>>(sm0_w, sm0_b, p_Ma, p_cva);

    // LayerNorm of tokens (independent of the above; overlaps via stream order anyway)
    ln_kernel<<<MTOK/8, 256>>>(x, norm_w, norm_b);

    // chain: M_i = diag(bm_i) * W_i @ M_{i-1} ; c_i = diag(bm_i)(W_i c_{i-1} + b_i)
    float* Mcur = p_Ma;  float* Mnxt = p_Mb;
    float* ccur = p_cva; float* cnxt = p_cvb;
    for (int i = 1; i < NLAYER; i++) {
        const float* Wi = smm_w + (size_t)(i-1)*HDIM*HDIM;
        const float* bi = smm_b + (size_t)(i-1)*HDIM;
        mm_f32<<<dim3(EDIM/32, HDIM/32), 256>>>(Wi, Mcur, p_bm + i*HDIM, Mnxt, HDIM, EDIM, HDIM);
        mv_f32<<<1, 512>>>(Wi, ccur, bi, p_bm + i*HDIM, cnxt, HDIM, HDIM);
        float* t;
        t = Mcur; Mcur = Mnxt; Mnxt = t;
        t = ccur; ccur = cnxt; cnxt = t;
    }
    // W_total = sml_w @ M6 ; c_total = sml_w @ c6 + sml_b
    mm_f32<<<dim3(EDIM/32, EDIM/32), 256>>>(sml_w, Mcur, nullptr, p_Wt, EDIM, EDIM, HDIM);
    mv_f32<<<1, 512>>>(sml_w, ccur, sml_b, nullptr, p_ct, EDIM, HDIM);
    conv_kernel<<<80, 256>>>(p_Wt, p_wtb, EDIM*EDIM);

    // ---- token compute: ONE E->E GEMM with fused sigmoid*xn, then head ----
    gemm_k<160,1><<<dim3(MTOK/BM_T, EDIM/160), 512, SMEM_G>>>(
        p_xnb, p_wtb, p_ct, p_xnf, p_xgf, MTOK, EDIM, EDIM);
    head_kernel<<<MTOK/128, 256>>>(p_xgf, head_w, head_b, (float*)d_out);
}

// round 11
// speedup vs baseline: 10.1757x; 6.4311x over previous
#include <cuda_runtime.h>
#include <cuda_bf16.h>
#include <cstdint>

// ---------------- problem constants ----------------
#define BATCH 64
#define LSEQ  1024
#define EDIM  320
#define HDIM  480
#define CDIM  32
#define NLAYER 7
#define MTOK  (BATCH*LSEQ)   // 65536
#define AUGN  352            // 320 composite cols + 1 bias col + 31 pad

// ---------------- device scratch ----------------
__device__ float          g_bm[NLAYER*HDIM];
__device__ float          g_Ma[HDIM*AUGN];     // composite ping [480,352]
__device__ float          g_Mb[HDIM*AUGN];     // composite pong
__device__ float          g_ct[EDIM];          // final composite bias
__device__ __nv_bfloat16  g_wtb[EDIM*EDIM];    // final composite weight bf16
__device__ float          g_xnf[(size_t)MTOK*EDIM];
__device__ __nv_bfloat16  g_xnb[(size_t)MTOK*EDIM];
__device__ float          g_xgf[(size_t)MTOK*EDIM];

// ---------------- bm: one CTA per layer, warp-per-row coalesced ----------------
__global__ __launch_bounds__(512) void bm_kernel(
    const float* __restrict__ snr,
    const float* __restrict__ w1, const float* __restrict__ b1,
    const float* __restrict__ w2, const float* __restrict__ b2,
    const float* __restrict__ w3, const float* __restrict__ b3)
{
    const int i = blockIdx.x;              // layer
    __shared__ float h1[HDIM];
    __shared__ float h2[HDIM];
    const int tid  = threadIdx.x;
    const int warp = tid >> 5;
    const int lane = tid & 31;
    const float s = snr[0];

    for (int j = tid; j < HDIM; j += 512)
        h1[j] = fmaxf(0.f, s * w1[i*HDIM + j] + b1[i*HDIM + j]);
    __syncthreads();

    for (int j = warp; j < HDIM; j += 16) {
        const float* w = w2 + ((size_t)i*HDIM + j) * HDIM;
        float acc = 0.f;
        #pragma unroll
        for (int k = lane; k < HDIM; k += 32) acc += w[k] * h1[k];
        #pragma unroll
        for (int o = 16; o > 0; o >>= 1) acc += __shfl_xor_sync(0xffffffffu, acc, o);
        if (lane == 0) h2[j] = fmaxf(0.f, acc + b2[i*HDIM + j]);
    }
    __syncthreads();

    for (int j = warp; j < HDIM; j += 16) {
        const float* w = w3 + ((size_t)i*HDIM + j) * HDIM;
        float acc = 0.f;
        #pragma unroll
        for (int k = lane; k < HDIM; k += 32) acc += w[k] * h2[k];
        #pragma unroll
        for (int o = 16; o > 0; o >>= 1) acc += __shfl_xor_sync(0xffffffffu, acc, o);
        if (lane == 0) g_bm[i*HDIM + j] = 1.f / (1.f + expf(-(acc + b3[i*HDIM + j])));
    }
}

// M0aug = [diag(bm0)*sm0_w | bm0*sm0_b | 0]
__global__ void diag0_kernel(const float* __restrict__ w, const float* __restrict__ b)
{
    const int stride = gridDim.x * blockDim.x;
    for (int i = blockIdx.x * blockDim.x + threadIdx.x; i < HDIM*AUGN; i += stride) {
        const int r = i / AUGN, c = i - r * AUGN;
        float v;
        if (c < EDIM)       v = g_bm[r] * w[r*EDIM + c];
        else if (c == EDIM) v = g_bm[r] * b[r];
        else                v = 0.f;
        g_Ma[i] = v;
    }
}

// C[M,AUGN] = diag(rs?) * (A[M,K] @ B[K,AUGN] + e_320 (x) bvec)
// Block 256 = 16x16, tile 32x32 (2x2/thread), K-chunk 32, double-buffered.
__global__ __launch_bounds__(256) void mm_aug(
    const float* __restrict__ A, const float* __restrict__ B,
    const float* __restrict__ rs, const float* __restrict__ bvec,
    float* __restrict__ C, int M, int K)
{
    __shared__ float As[2][32][33];
    __shared__ float Bs[2][32][33];
    const int tid = threadIdx.x;
    const int tx = tid & 15, ty = tid >> 4;
    const int r0 = blockIdx.y * 32, c0 = blockIdx.x * 32;
    const int lr = tid >> 3;          // 0..31 (row in tile)
    const int lc = (tid & 7) * 4;     // 0,4,..,28 (col quad)
    const int KT = K / 32;

    auto fetch = [&](int kt, float4& fa, float4& fb) {
        fa = *(const float4*)(A + (size_t)(r0 + lr) * K + kt*32 + lc);
        fb = *(const float4*)(B + (size_t)(kt*32 + lr) * AUGN + c0 + lc);
    };
    auto store = [&](int buf, const float4& fa, const float4& fb) {
        As[buf][lr][lc]   = fa.x; As[buf][lr][lc+1] = fa.y;
        As[buf][lr][lc+2] = fa.z; As[buf][lr][lc+3] = fa.w;
        Bs[buf][lr][lc]   = fb.x; Bs[buf][lr][lc+1] = fb.y;
        Bs[buf][lr][lc+2] = fb.z; Bs[buf][lr][lc+3] = fb.w;
    };

    float4 fa, fb;
    fetch(0, fa, fb);
    store(0, fa, fb);
    __syncthreads();

    float acc00 = 0.f, acc01 = 0.f, acc10 = 0.f, acc11 = 0.f;
    for (int kt = 0; kt < KT; kt++) {
        const int cur = kt & 1;
        if (kt + 1 < KT) fetch(kt + 1, fa, fb);
        #pragma unroll
        for (int k = 0; k < 32; k++) {
            const float a0 = As[cur][ty*2][k],   a1 = As[cur][ty*2+1][k];
            const float b0 = Bs[cur][k][tx*2],   b1 = Bs[cur][k][tx*2+1];
            acc00 += a0*b0; acc01 += a0*b1;
            acc10 += a1*b0; acc11 += a1*b1;
        }
        if (kt + 1 < KT) {
            store(cur ^ 1, fa, fb);
            __syncthreads();
        }
    }

    const int ra = r0 + ty*2, rb = ra + 1;
    const int ca = c0 + tx*2, cb = ca + 1;
    const float s0 = rs ? rs[ra] : 1.f;
    const float s1 = rs ? rs[rb] : 1.f;
    const float ba0 = (ca == EDIM) ? bvec[ra] : 0.f;
    const float bb0 = (cb == EDIM) ? bvec[ra] : 0.f;
    const float ba1 = (ca == EDIM) ? bvec[rb] : 0.f;
    const float bb1 = (cb == EDIM) ? bvec[rb] : 0.f;
    C[(size_t)ra * AUGN + ca] = s0 * (acc00 + ba0);
    C[(size_t)ra * AUGN + cb] = s0 * (acc01 + bb0);
    C[(size_t)rb * AUGN + ca] = s1 * (acc10 + ba1);
    C[(size_t)rb * AUGN + cb] = s1 * (acc11 + bb1);
}

// extract bf16 weight + bias column from final augmented composite
__global__ void extract_kernel(const float* __restrict__ Mfin)
{
    const int stride = gridDim.x * blockDim.x;
    const int idx0 = blockIdx.x * blockDim.x + threadIdx.x;
    for (int i = idx0; i < EDIM*EDIM; i += stride) {
        const int r = i / EDIM, c = i - r * EDIM;
        g_wtb[i] = __float2bfloat16(Mfin[(size_t)r * AUGN + c]);
    }
    if (idx0 < EDIM) g_ct[idx0] = Mfin[(size_t)idx0 * AUGN + EDIM];
}

// LayerNorm: one warp per token. fp32 + bf16 copies.
__global__ void ln_kernel(const float* __restrict__ x,
                          const float* __restrict__ w, const float* __restrict__ b)
{
    const int warp = threadIdx.x >> 5;
    const int lane = threadIdx.x & 31;
    const size_t t = (size_t)blockIdx.x * 8 + warp;
    const float* xp = x + t * EDIM;
    float v[10];
    float s = 0.f, s2 = 0.f;
    #pragma unroll
    for (int i = 0; i < 10; i++) {
        v[i] = xp[lane + 32*i];
        s  += v[i];
        s2 += v[i]*v[i];
    }
    #pragma unroll
    for (int o = 16; o > 0; o >>= 1) {
        s  += __shfl_xor_sync(0xffffffffu, s,  o);
        s2 += __shfl_xor_sync(0xffffffffu, s2, o);
    }
    const float mu  = s  * (1.f/EDIM);
    const float var = s2 * (1.f/EDIM) - mu*mu;
    const float inv = 1.f / sqrtf(var + 1e-5f);
    #pragma unroll
    for (int i = 0; i < 10; i++) {
        const int c = lane + 32*i;
        const float y = (v[i] - mu) * inv * w[c] + b[c];
        g_xnf[t*EDIM + c] = y;
        g_xnb[t*EDIM + c] = __float2bfloat16(y);
    }
}

// ---------------- GEMM: C = sigmoid(A @ W^T + ct) * xn -> fp32 ----------------
#define BM_T 128
#define BK_T 32
#define LDT  (BK_T + 8)
#define STAGES 4

__device__ __forceinline__ void cp16(uint32_t s, const void* g) {
    asm volatile("cp.async.cg.shared.global [%0], [%1], 16;" :: "r"(s), "l"(g));
}
__device__ __forceinline__ void ldm4(uint32_t a, uint32_t& r0, uint32_t& r1, uint32_t& r2, uint32_t& r3) {
    asm volatile("ldmatrix.sync.aligned.m8n8.x4.shared.b16 {%0,%1,%2,%3}, [%4];"
                 : "=r"(r0), "=r"(r1), "=r"(r2), "=r"(r3) : "r"(a));
}
__device__ __forceinline__ void ldm2(uint32_t a, uint32_t& r0, uint32_t& r1) {
    asm volatile("ldmatrix.sync.aligned.m8n8.x2.shared.b16 {%0,%1}, [%2];"
                 : "=r"(r0), "=r"(r1) : "r"(a));
}
__device__ __forceinline__ void mma16816(float* c, const uint32_t* a, const uint32_t* b) {
    asm volatile("mma.sync.aligned.m16n8k16.row.col.f32.bf16.bf16.f32 "
                 "{%0,%1,%2,%3}, {%4,%5,%6,%7}, {%8,%9}, {%0,%1,%2,%3};"
                 : "+f"(c[0]), "+f"(c[1]), "+f"(c[2]), "+f"(c[3])
                 : "r"(a[0]), "r"(a[1]), "r"(a[2]), "r"(a[3]), "r"(b[0]), "r"(b[1]));
}

template<int BN>
__global__ __launch_bounds__(512, 1) void gemm_k(
    const __nv_bfloat16* __restrict__ A, const __nv_bfloat16* __restrict__ W,
    const float* __restrict__ bias, const float* __restrict__ xnf,
    float* __restrict__ Cout, int M, int N, int K)
{
    constexpr int NIW  = BN / 32;
    constexpr int ASTG = BM_T * LDT;
    constexpr int BSTG = BN * LDT;

    extern __shared__ __align__(16) __nv_bfloat16 smem[];
    __nv_bfloat16* Asm = smem;
    __nv_bfloat16* Bsm = smem + STAGES * ASTG;

    const int tid  = threadIdx.x;
    const int lane = tid & 31;
    const int warp = tid >> 5;
    const int wr = warp & 3;
    const int wc = warp >> 2;

    const uint32_t sA = (uint32_t)__cvta_generic_to_shared(Asm);
    const uint32_t sB = (uint32_t)__cvta_generic_to_shared(Bsm);
    const size_t Arow0 = (size_t)blockIdx.x * BM_T;
    const size_t Brow0 = (size_t)blockIdx.y * BN;
    const int KT = K / BK_T;

    auto load_st = [&](int kt, int buf) {
        const __nv_bfloat16* Ag = A + Arow0 * K + (size_t)kt * BK_T;
        const uint32_t sa = sA + buf * (ASTG * 2);
        for (int id = tid; id < BM_T * 4; id += 512) {
            const int r = id >> 2, c = (id & 3) * 8;
            cp16(sa + (r * LDT + c) * 2, Ag + (size_t)r * K + c);
        }
        const __nv_bfloat16* Bg = W + Brow0 * K + (size_t)kt * BK_T;
        const uint32_t sb = sB + buf * (BSTG * 2);
        for (int id = tid; id < BN * 4; id += 512) {
            const int r = id >> 2, c = (id & 3) * 8;
            cp16(sb + (r * LDT + c) * 2, Bg + (size_t)r * K + c);
        }
        asm volatile("cp.async.commit_group;");
    };

    float acc[2][NIW][4];
    #pragma unroll
    for (int mi = 0; mi < 2; mi++)
        #pragma unroll
        for (int ni = 0; ni < NIW; ni++)
            #pragma unroll
            for (int e = 0; e < 4; e++) acc[mi][ni][e] = 0.f;

    load_st(0, 0);
    load_st(1, 1);
    load_st(2, 2);

    for (int kt = 0; kt < KT; kt++) {
        const int rem = KT - 1 - kt;
        if (rem >= 2)      asm volatile("cp.async.wait_group 2;");
        else if (rem == 1) asm volatile("cp.async.wait_group 1;");
        else               asm volatile("cp.async.wait_group 0;");
        __syncthreads();

        if (kt + 3 < KT) load_st(kt + 3, (kt + 3) & 3);

        const int buf = kt & 3;
        const uint32_t baseA = sA + buf * (ASTG * 2);
        const uint32_t baseB = sB + buf * (BSTG * 2);
        #pragma unroll
        for (int ks = 0; ks < 2; ks++) {
            uint32_t af[2][4];
            #pragma unroll
            for (int mi = 0; mi < 2; mi++) {
                const int row = wr * 32 + mi * 16 + (lane & 15);
                const int col = ks * 16 + (lane >> 4) * 8;
                ldm4(baseA + (row * LDT + col) * 2, af[mi][0], af[mi][1], af[mi][2], af[mi][3]);
            }
            uint32_t bf[NIW][2];
            #pragma unroll
            for (int np = 0; np < NIW / 2; np++) {
                const int row = wc * (BN / 4) + np * 16 + (lane & 7) + ((lane >> 4) << 3);
                const int col = ks * 16 + (((lane >> 3) & 1) << 3);
                ldm4(baseB + (row * LDT + col) * 2,
                     bf[2*np][0], bf[2*np][1], bf[2*np+1][0], bf[2*np+1][1]);
            }
            if (NIW & 1) {
                const int l = lane & 15;
                const int row = wc * (BN / 4) + (NIW - 1) * 8 + (l & 7);
                const int col = ks * 16 + ((l >> 3) << 3);
                ldm2(baseB + (row * LDT + col) * 2, bf[NIW-1][0], bf[NIW-1][1]);
            }
            #pragma unroll
            for (int mi = 0; mi < 2; mi++)
                #pragma unroll
                for (int ni = 0; ni < NIW; ni++)
                    mma16816(acc[mi][ni], af[mi], bf[ni]);
        }
    }

    const size_t mb = Arow0 + wr * 32;
    const int nb = (int)Brow0 + wc * (BN / 4);
    #pragma unroll
    for (int mi = 0; mi < 2; mi++) {
        #pragma unroll
        for (int ni = 0; ni < NIW; ni++) {
            const size_t m0 = mb + mi * 16 + (lane >> 2);
            const int n0 = nb + ni * 8 + (lane & 3) * 2;
            #pragma unroll
            for (int e = 0; e < 4; e++) {
                const size_t m = m0 + ((e >= 2) ? 8 : 0);
                const int n = n0 + (e & 1);
                const float v = acc[mi][ni][e] + bias[n];
                const float sg = 1.f / (1.f + __expf(-v));
                Cout[m * N + n] = sg * xnf[m * N + n];
            }
        }
    }
}

// ---------------- head GEMM: fp32, M=65536 N=32 K=320 ----------------
__global__ __launch_bounds__(256, 2) void head_kernel(
    const float* __restrict__ A, const float* __restrict__ W,
    const float* __restrict__ bias, float* __restrict__ out)
{
    __shared__ float ws[EDIM * CDIM];
    __shared__ float as[32 * 128];

    const int tid = threadIdx.x;
    for (int i = tid; i < EDIM * CDIM; i += 256) {
        const int c = i & 31;
        const int k = i >> 5;
        ws[k * CDIM + c] = W[c * EDIM + k];
    }

    const size_t row0 = (size_t)blockIdx.x * 128;
    const int rg = tid >> 3;
    const int cg = tid & 7;

    float acc[4][4];
    #pragma unroll
    for (int i = 0; i < 4; i++)
        #pragma unroll
        for (int j = 0; j < 4; j++) acc[i][j] = 0.f;

    for (int k0 = 0; k0 < EDIM; k0 += 32) {
        __syncthreads();
        #pragma unroll
        for (int i = 0; i < 4; i++) {
            const int idx = tid + 256 * i;
            const int r  = idx & 127;
            const int kq = idx >> 7;
            const float4 v = *(const float4*)(A + (row0 + r) * EDIM + k0 + kq * 4);
            as[(kq * 4 + 0) * 128 + r] = v.x;
            as[(kq * 4 + 1) * 128 + r] = v.y;
            as[(kq * 4 + 2) * 128 + r] = v.z;
            as[(kq * 4 + 3) * 128 + r] = v.w;
        }
        __syncthreads();
        #pragma unroll
        for (int k = 0; k < 32; k++) {
            const float4 av = *(const float4*)(as + k * 128 + rg * 4);
            const float4 bv = *(const float4*)(ws + (k0 + k) * CDIM + cg * 4);
            acc[0][0] += av.x * bv.x; acc[0][1] += av.x * bv.y;
            acc[0][2] += av.x * bv.z; acc[0][3] += av.x * bv.w;
            acc[1][0] += av.y * bv.x; acc[1][1] += av.y * bv.y;
            acc[1][2] += av.y * bv.z; acc[1][3] += av.y * bv.w;
            acc[2][0] += av.z * bv.x; acc[2][1] += av.z * bv.y;
            acc[2][2] += av.z * bv.z; acc[2][3] += av.z * bv.w;
            acc[3][0] += av.w * bv.x; acc[3][1] += av.w * bv.y;
            acc[3][2] += av.w * bv.z; acc[3][3] += av.w * bv.w;
        }
    }

    const float4 bv = *(const float4*)(bias + cg * 4);
    #pragma unroll
    for (int i = 0; i < 4; i++) {
        float4 o;
        o.x = acc[i][0] + bv.x;
        o.y = acc[i][1] + bv.y;
        o.z = acc[i][2] + bv.z;
        o.w = acc[i][3] + bv.w;
        *(float4*)(out + (row0 + rg * 4 + i) * CDIM + cg * 4) = o;
    }
}

// ---------------- launch ----------------
extern "C" void kernel_launch(void* const* d_in, const int* in_sizes, int n_in,
                              void* d_out, int out_size)
{
    (void)in_sizes; (void)n_in; (void)out_size;
    const float* x       = (const float*)d_in[0];
    const float* snr     = (const float*)d_in[1];
    const float* norm_w  = (const float*)d_in[2];
    const float* norm_b  = (const float*)d_in[3];
    const float* sm0_w   = (const float*)d_in[4];
    const float* sm0_b   = (const float*)d_in[5];
    const float* smm_w   = (const float*)d_in[6];
    const float* smm_b   = (const float*)d_in[7];
    const float* sml_w   = (const float*)d_in[8];
    const float* sml_b   = (const float*)d_in[9];
    const float* bm_w1   = (const float*)d_in[10];
    const float* bm_b1   = (const float*)d_in[11];
    const float* bm_w2   = (const float*)d_in[12];
    const float* bm_b2   = (const float*)d_in[13];
    const float* bm_w3   = (const float*)d_in[14];
    const float* bm_b3   = (const float*)d_in[15];
    const float* head_w  = (const float*)d_in[16];
    const float* head_b  = (const float*)d_in[17];

    float *p_bm, *p_Ma, *p_Mb, *p_ct, *p_xnf, *p_xgf;
    __nv_bfloat16 *p_wtb, *p_xnb;
    cudaGetSymbolAddress((void**)&p_bm,  g_bm);
    cudaGetSymbolAddress((void**)&p_Ma,  g_Ma);
    cudaGetSymbolAddress((void**)&p_Mb,  g_Mb);
    cudaGetSymbolAddress((void**)&p_ct,  g_ct);
    cudaGetSymbolAddress((void**)&p_wtb, g_wtb);
    cudaGetSymbolAddress((void**)&p_xnf, g_xnf);
    cudaGetSymbolAddress((void**)&p_xnb, g_xnb);
    cudaGetSymbolAddress((void**)&p_xgf, g_xgf);

    constexpr int SMEM_G = STAGES * (BM_T + 160) * LDT * 2;  // 92160 B
    cudaFuncSetAttribute(gemm_k<160>, cudaFuncAttributeMaxDynamicSharedMemorySize, SMEM_G);

    // ---- token-independent precompute (now all parallel-friendly) ----
    bm_kernel<<<NLAYER, 512>>>(snr, bm_w1, bm_b1, bm_w2, bm_b2, bm_w3, bm_b3);
    diag0_kernel<<<240, 256>>>(sm0_w, sm0_b);
    ln_kernel<<<MTOK/8, 256>>>(x, norm_w, norm_b);

    // composite chain with fused bias column: [M|c] ping-pong
    float* Mcur = p_Ma;  float* Mnxt = p_Mb;
    for (int i = 1; i < NLAYER; i++) {
        mm_aug<<<dim3(AUGN/32, HDIM/32), 256>>>(
            smm_w + (size_t)(i-1)*HDIM*HDIM, Mcur,
            p_bm + i*HDIM, smm_b + (size_t)(i-1)*HDIM, Mnxt, HDIM, HDIM);
        float* t = Mcur; Mcur = Mnxt; Mnxt = t;
    }
    // final: sml_w @ [M6|c6] + sml_b on bias col (no gate)
    mm_aug<<<dim3(AUGN/32, EDIM/32), 256>>>(
        sml_w, Mcur, nullptr, sml_b, Mnxt, EDIM, HDIM);
    extract_kernel<<<160, 256>>>(Mnxt);

    // ---- token compute: ONE fused E->E GEMM, then head ----
    gemm_k<160><<<dim3(MTOK/BM_T, EDIM/160), 512, SMEM_G>>>(
        p_xnb, p_wtb, p_ct, p_xnf, p_xgf, MTOK, EDIM, EDIM);
    head_kernel<<<MTOK/128, 256>>>(p_xgf, head_w, head_b, (float*)d_out);
}

// round 12
// speedup vs baseline: 10.3980x; 1.0218x over previous
#include <cuda_runtime.h>
#include <cuda_bf16.h>
#include <cstdint>

// ---------------- problem constants ----------------
#define BATCH 64
#define LSEQ  1024
#define EDIM  320
#define HDIM  480
#define CDIM  32
#define NLAYER 7
#define MTOK  (BATCH*LSEQ)   // 65536
#define ADIM  512            // augmented matrix size (481 used, padded)
#define MS    (ADIM*ADIM)    // elements per slot

// ---------------- device scratch ----------------
__device__ float          g_bm[NLAYER*HDIM];
// slots 0..7: inputs (Wl~,A6~,A5~,A4~,A3~,A2~,A1~,M0~); 8..11 L1; 12..13 L2; 14 final
__device__ float          g_mat[15*MS];
__device__ float          g_ct[EDIM];
__device__ __nv_bfloat16  g_wtb[EDIM*EDIM];
__device__ float          g_xnf[(size_t)MTOK*EDIM];
__device__ __nv_bfloat16  g_xnb[(size_t)MTOK*EDIM];
__device__ float          g_xgf[(size_t)MTOK*EDIM];

// ---------------- bm: one CTA per layer, warp-per-row coalesced ----------------
__global__ __launch_bounds__(512) void bm_kernel(
    const float* __restrict__ snr,
    const float* __restrict__ w1, const float* __restrict__ b1,
    const float* __restrict__ w2, const float* __restrict__ b2,
    const float* __restrict__ w3, const float* __restrict__ b3)
{
    const int i = blockIdx.x;
    __shared__ float h1[HDIM];
    __shared__ float h2[HDIM];
    const int tid  = threadIdx.x;
    const int warp = tid >> 5;
    const int lane = tid & 31;
    const float s = snr[0];

    for (int j = tid; j < HDIM; j += 512)
        h1[j] = fmaxf(0.f, s * w1[i*HDIM + j] + b1[i*HDIM + j]);
    __syncthreads();

    for (int j = warp; j < HDIM; j += 16) {
        const float* w = w2 + ((size_t)i*HDIM + j) * HDIM;
        float acc = 0.f;
        for (int k = lane; k < HDIM; k += 32) acc += w[k] * h1[k];
        #pragma unroll
        for (int o = 16; o > 0; o >>= 1) acc += __shfl_xor_sync(0xffffffffu, acc, o);
        if (lane == 0) h2[j] = fmaxf(0.f, acc + b2[i*HDIM + j]);
    }
    __syncthreads();

    for (int j = warp; j < HDIM; j += 16) {
        const float* w = w3 + ((size_t)i*HDIM + j) * HDIM;
        float acc = 0.f;
        for (int k = lane; k < HDIM; k += 32) acc += w[k] * h2[k];
        #pragma unroll
        for (int o = 16; o > 0; o >>= 1) acc += __shfl_xor_sync(0xffffffffu, acc, o);
        if (lane == 0) g_bm[i*HDIM + j] = 1.f / (1.f + expf(-(acc + b3[i*HDIM + j])));
    }
}

// ---------------- materialize the 8 augmented matrices ----------------
// product needed: Wl~ (slot0) . A6~ . A5~ . A4~ . A3~ . A2~ . A1~ (slot6) . M0~ (slot7)
// Augmented vector = [temp(480); 1] (index 480). For M0~ input vec = [xn(320); 1] (index 320).
__global__ void materialize_kernel(
    const float* __restrict__ sm0_w, const float* __restrict__ sm0_b,
    const float* __restrict__ smm_w, const float* __restrict__ smm_b,
    const float* __restrict__ sml_w, const float* __restrict__ sml_b)
{
    const long stride = (long)gridDim.x * blockDim.x;
    for (long idx = (long)blockIdx.x * blockDim.x + threadIdx.x; idx < 8L*MS; idx += stride) {
        const int slot = (int)(idx / MS);
        const int e = (int)(idx - (long)slot * MS);
        const int r = e >> 9;          // /512
        const int c = e & 511;
        float v = 0.f;
        if (slot == 0) {               // Wl~: [[sml_w(320x480) | sml_b @ col480],[row320: 1 @ col480]]
            if (r < EDIM) {
                if (c < HDIM)       v = sml_w[r*HDIM + c];
                else if (c == HDIM) v = sml_b[r];
            } else if (r == EDIM && c == HDIM) v = 1.f;
        } else if (slot <= 6) {        // A_i~, i = 7-slot (slot1=A6 ... slot6=A1)
            const int i = 7 - slot;
            if (r < HDIM) {
                const float g = g_bm[i*HDIM + r];
                if (c < HDIM)       v = g * smm_w[((size_t)(i-1)*HDIM + r)*HDIM + c];
                else if (c == HDIM) v = g * smm_b[(i-1)*HDIM + r];
            } else if (r == HDIM && c == HDIM) v = 1.f;
        } else {                       // M0~: [[diag(bm0)sm0_w(480x320) | diag(bm0)sm0_b @ col320],[row480: 1 @ col320]]
            if (r < HDIM) {
                const float g = g_bm[r];
                if (c < EDIM)       v = g * sm0_w[r*EDIM + c];
                else if (c == EDIM) v = g * sm0_b[r];
            } else if (r == HDIM && c == EDIM) v = 1.f;
        }
        g_mat[idx] = v;
    }
}

// ---------------- batched 512x512x512 fp32 GEMM: C = A @ B ----------------
// block 256 = 16x16, 32x32 tile (2x2/thread), K-chunk 32, double-buffered regs.
__global__ __launch_bounds__(256) void mm3(
    const float* __restrict__ Ab, int Asz,
    const float* __restrict__ Bb, int Bsz,
    float* __restrict__ Cb, int Csz)
{
    const float* A = Ab + (size_t)blockIdx.z * Asz;
    const float* B = Bb + (size_t)blockIdx.z * Bsz;
    float*       C = Cb + (size_t)blockIdx.z * Csz;

    __shared__ float As[2][32][33];
    __shared__ float Bs[2][32][33];
    const int tid = threadIdx.x;
    const int tx = tid & 15, ty = tid >> 4;
    const int r0 = blockIdx.y * 32, c0 = blockIdx.x * 32;
    const int lr = tid >> 3;
    const int lc = (tid & 7) * 4;

    auto fetch = [&](int kt, float4& fa, float4& fb) {
        fa = *(const float4*)(A + (size_t)(r0 + lr) * ADIM + kt*32 + lc);
        fb = *(const float4*)(B + (size_t)(kt*32 + lr) * ADIM + c0 + lc);
    };
    auto store = [&](int buf, const float4& fa, const float4& fb) {
        As[buf][lr][lc]   = fa.x; As[buf][lr][lc+1] = fa.y;
        As[buf][lr][lc+2] = fa.z; As[buf][lr][lc+3] = fa.w;
        Bs[buf][lr][lc]   = fb.x; Bs[buf][lr][lc+1] = fb.y;
        Bs[buf][lr][lc+2] = fb.z; Bs[buf][lr][lc+3] = fb.w;
    };

    float4 fa, fb;
    fetch(0, fa, fb);
    store(0, fa, fb);
    __syncthreads();

    float acc00 = 0.f, acc01 = 0.f, acc10 = 0.f, acc11 = 0.f;
    const int KT = ADIM / 32;
    for (int kt = 0; kt < KT; kt++) {
        const int cur = kt & 1;
        if (kt + 1 < KT) fetch(kt + 1, fa, fb);
        #pragma unroll
        for (int k = 0; k < 32; k++) {
            const float a0 = As[cur][ty*2][k],   a1 = As[cur][ty*2+1][k];
            const float b0 = Bs[cur][k][tx*2],   b1 = Bs[cur][k][tx*2+1];
            acc00 += a0*b0; acc01 += a0*b1;
            acc10 += a1*b0; acc11 += a1*b1;
        }
        if (kt + 1 < KT) {
            store(cur ^ 1, fa, fb);
            __syncthreads();
        }
    }

    const int ra = r0 + ty*2, ca = c0 + tx*2;
    C[(size_t)ra     * ADIM + ca]     = acc00;
    C[(size_t)ra     * ADIM + ca + 1] = acc01;
    C[(size_t)(ra+1) * ADIM + ca]     = acc10;
    C[(size_t)(ra+1) * ADIM + ca + 1] = acc11;
}

// extract bf16 weight + bias column from final composite (slot 14)
__global__ void extract_kernel()
{
    const float* T = g_mat + 14*MS;
    const int stride = gridDim.x * blockDim.x;
    const int idx0 = blockIdx.x * blockDim.x + threadIdx.x;
    for (int i = idx0; i < EDIM*EDIM; i += stride) {
        const int r = i / EDIM, c = i - r * EDIM;
        g_wtb[i] = __float2bfloat16(T[(size_t)r * ADIM + c]);
    }
    if (idx0 < EDIM) g_ct[idx0] = T[(size_t)idx0 * ADIM + EDIM];
}

// LayerNorm: one warp per token. fp32 + bf16 copies.
__global__ void ln_kernel(const float* __restrict__ x,
                          const float* __restrict__ w, const float* __restrict__ b)
{
    const int warp = threadIdx.x >> 5;
    const int lane = threadIdx.x & 31;
    const size_t t = (size_t)blockIdx.x * 8 + warp;
    const float* xp = x + t * EDIM;
    float v[10];
    float s = 0.f, s2 = 0.f;
    #pragma unroll
    for (int i = 0; i < 10; i++) {
        v[i] = xp[lane + 32*i];
        s  += v[i];
        s2 += v[i]*v[i];
    }
    #pragma unroll
    for (int o = 16; o > 0; o >>= 1) {
        s  += __shfl_xor_sync(0xffffffffu, s,  o);
        s2 += __shfl_xor_sync(0xffffffffu, s2, o);
    }
    const float mu  = s  * (1.f/EDIM);
    const float var = s2 * (1.f/EDIM) - mu*mu;
    const float inv = 1.f / sqrtf(var + 1e-5f);
    #pragma unroll
    for (int i = 0; i < 10; i++) {
        const int c = lane + 32*i;
        const float y = (v[i] - mu) * inv * w[c] + b[c];
        g_xnf[t*EDIM + c] = y;
        g_xnb[t*EDIM + c] = __float2bfloat16(y);
    }
}

// ---------------- GEMM: C = sigmoid(A @ W^T + ct) * xn -> fp32 ----------------
#define BM_T 128
#define BK_T 32
#define LDT  (BK_T + 8)
#define STAGES 4

__device__ __forceinline__ void cp16(uint32_t s, const void* g) {
    asm volatile("cp.async.cg.shared.global [%0], [%1], 16;" :: "r"(s), "l"(g));
}
__device__ __forceinline__ void ldm4(uint32_t a, uint32_t& r0, uint32_t& r1, uint32_t& r2, uint32_t& r3) {
    asm volatile("ldmatrix.sync.aligned.m8n8.x4.shared.b16 {%0,%1,%2,%3}, [%4];"
                 : "=r"(r0), "=r"(r1), "=r"(r2), "=r"(r3) : "r"(a));
}
__device__ __forceinline__ void ldm2(uint32_t a, uint32_t& r0, uint32_t& r1) {
    asm volatile("ldmatrix.sync.aligned.m8n8.x2.shared.b16 {%0,%1}, [%2];"
                 : "=r"(r0), "=r"(r1) : "r"(a));
}
__device__ __forceinline__ void mma16816(float* c, const uint32_t* a, const uint32_t* b) {
    asm volatile("mma.sync.aligned.m16n8k16.row.col.f32.bf16.bf16.f32 "
                 "{%0,%1,%2,%3}, {%4,%5,%6,%7}, {%8,%9}, {%0,%1,%2,%3};"
                 : "+f"(c[0]), "+f"(c[1]), "+f"(c[2]), "+f"(c[3])
                 : "r"(a[0]), "r"(a[1]), "r"(a[2]), "r"(a[3]), "r"(b[0]), "r"(b[1]));
}

template<int BN>
__global__ __launch_bounds__(512, 1) void gemm_k(
    const __nv_bfloat16* __restrict__ A, const __nv_bfloat16* __restrict__ W,
    const float* __restrict__ bias, const float* __restrict__ xnf,
    float* __restrict__ Cout, int M, int N, int K)
{
    constexpr int NIW  = BN / 32;
    constexpr int ASTG = BM_T * LDT;
    constexpr int BSTG = BN * LDT;

    extern __shared__ __align__(16) __nv_bfloat16 smem[];
    __nv_bfloat16* Asm = smem;
    __nv_bfloat16* Bsm = smem + STAGES * ASTG;

    const int tid  = threadIdx.x;
    const int lane = tid & 31;
    const int warp = tid >> 5;
    const int wr = warp & 3;
    const int wc = warp >> 2;

    const uint32_t sA = (uint32_t)__cvta_generic_to_shared(Asm);
    const uint32_t sB = (uint32_t)__cvta_generic_to_shared(Bsm);
    const size_t Arow0 = (size_t)blockIdx.x * BM_T;
    const size_t Brow0 = (size_t)blockIdx.y * BN;
    const int KT = K / BK_T;

    auto load_st = [&](int kt, int buf) {
        const __nv_bfloat16* Ag = A + Arow0 * K + (size_t)kt * BK_T;
        const uint32_t sa = sA + buf * (ASTG * 2);
        for (int id = tid; id < BM_T * 4; id += 512) {
            const int r = id >> 2, c = (id & 3) * 8;
            cp16(sa + (r * LDT + c) * 2, Ag + (size_t)r * K + c);
        }
        const __nv_bfloat16* Bg = W + Brow0 * K + (size_t)kt * BK_T;
        const uint32_t sb = sB + buf * (BSTG * 2);
        for (int id = tid; id < BN * 4; id += 512) {
            const int r = id >> 2, c = (id & 3) * 8;
            cp16(sb + (r * LDT + c) * 2, Bg + (size_t)r * K + c);
        }
        asm volatile("cp.async.commit_group;");
    };

    float acc[2][NIW][4];
    #pragma unroll
    for (int mi = 0; mi < 2; mi++)
        #pragma unroll
        for (int ni = 0; ni < NIW; ni++)
            #pragma unroll
            for (int e = 0; e < 4; e++) acc[mi][ni][e] = 0.f;

    load_st(0, 0);
    load_st(1, 1);
    load_st(2, 2);

    for (int kt = 0; kt < KT; kt++) {
        const int rem = KT - 1 - kt;
        if (rem >= 2)      asm volatile("cp.async.wait_group 2;");
        else if (rem == 1) asm volatile("cp.async.wait_group 1;");
        else               asm volatile("cp.async.wait_group 0;");
        __syncthreads();

        if (kt + 3 < KT) load_st(kt + 3, (kt + 3) & 3);

        const int buf = kt & 3;
        const uint32_t baseA = sA + buf * (ASTG * 2);
        const uint32_t baseB = sB + buf * (BSTG * 2);
        #pragma unroll
        for (int ks = 0; ks < 2; ks++) {
            uint32_t af[2][4];
            #pragma unroll
            for (int mi = 0; mi < 2; mi++) {
                const int row = wr * 32 + mi * 16 + (lane & 15);
                const int col = ks * 16 + (lane >> 4) * 8;
                ldm4(baseA + (row * LDT + col) * 2, af[mi][0], af[mi][1], af[mi][2], af[mi][3]);
            }
            uint32_t bf[NIW][2];
            #pragma unroll
            for (int np = 0; np < NIW / 2; np++) {
                const int row = wc * (BN / 4) + np * 16 + (lane & 7) + ((lane >> 4) << 3);
                const int col = ks * 16 + (((lane >> 3) & 1) << 3);
                ldm4(baseB + (row * LDT + col) * 2,
                     bf[2*np][0], bf[2*np][1], bf[2*np+1][0], bf[2*np+1][1]);
            }
            if (NIW & 1) {
                const int l = lane & 15;
                const int row = wc * (BN / 4) + (NIW - 1) * 8 + (l & 7);
                const int col = ks * 16 + ((l >> 3) << 3);
                ldm2(baseB + (row * LDT + col) * 2, bf[NIW-1][0], bf[NIW-1][1]);
            }
            #pragma unroll
            for (int mi = 0; mi < 2; mi++)
                #pragma unroll
                for (int ni = 0; ni < NIW; ni++)
                    mma16816(acc[mi][ni], af[mi], bf[ni]);
        }
    }

    const size_t mb = Arow0 + wr * 32;
    const int nb = (int)Brow0 + wc * (BN / 4);
    #pragma unroll
    for (int mi = 0; mi < 2; mi++) {
        #pragma unroll
        for (int ni = 0; ni < NIW; ni++) {
            const size_t m0 = mb + mi * 16 + (lane >> 2);
            const int n0 = nb + ni * 8 + (lane & 3) * 2;
            #pragma unroll
            for (int e = 0; e < 4; e++) {
                const size_t m = m0 + ((e >= 2) ? 8 : 0);
                const int n = n0 + (e & 1);
                const float v = acc[mi][ni][e] + bias[n];
                const float sg = 1.f / (1.f + __expf(-v));
                Cout[m * N + n] = sg * xnf[m * N + n];
            }
        }
    }
}

// ---------------- head GEMM: fp32, M=65536 N=32 K=320 ----------------
__global__ __launch_bounds__(256, 2) void head_kernel(
    const float* __restrict__ A, const float* __restrict__ W,
    const float* __restrict__ bias, float* __restrict__ out)
{
    __shared__ float ws[EDIM * CDIM];
    __shared__ float as[32 * 128];

    const int tid = threadIdx.x;
    for (int i = tid; i < EDIM * CDIM; i += 256) {
        const int c = i & 31;
        const int k = i >> 5;
        ws[k * CDIM + c] = W[c * EDIM + k];
    }

    const size_t row0 = (size_t)blockIdx.x * 128;
    const int rg = tid >> 3;
    const int cg = tid & 7;

    float acc[4][4];
    #pragma unroll
    for (int i = 0; i < 4; i++)
        #pragma unroll
        for (int j = 0; j < 4; j++) acc[i][j] = 0.f;

    for (int k0 = 0; k0 < EDIM; k0 += 32) {
        __syncthreads();
        #pragma unroll
        for (int i = 0; i < 4; i++) {
            const int idx = tid + 256 * i;
            const int r  = idx & 127;
            const int kq = idx >> 7;
            const float4 v = *(const float4*)(A + (row0 + r) * EDIM + k0 + kq * 4);
            as[(kq * 4 + 0) * 128 + r] = v.x;
            as[(kq * 4 + 1) * 128 + r] = v.y;
            as[(kq * 4 + 2) * 128 + r] = v.z;
            as[(kq * 4 + 3) * 128 + r] = v.w;
        }
        __syncthreads();
        #pragma unroll
        for (int k = 0; k < 32; k++) {
            const float4 av = *(const float4*)(as + k * 128 + rg * 4);
            const float4 bv = *(const float4*)(ws + (k0 + k) * CDIM + cg * 4);
            acc[0][0] += av.x * bv.x; acc[0][1] += av.x * bv.y;
            acc[0][2] += av.x * bv.z; acc[0][3] += av.x * bv.w;
            acc[1][0] += av.y * bv.x; acc[1][1] += av.y * bv.y;
            acc[1][2] += av.y * bv.z; acc[1][3] += av.y * bv.w;
            acc[2][0] += av.z * bv.x; acc[2][1] += av.z * bv.y;
            acc[2][2] += av.z * bv.z; acc[2][3] += av.z * bv.w;
            acc[3][0] += av.w * bv.x; acc[3][1] += av.w * bv.y;
            acc[3][2] += av.w * bv.z; acc[3][3] += av.w * bv.w;
        }
    }

    const float4 bv = *(const float4*)(bias + cg * 4);
    #pragma unroll
    for (int i = 0; i < 4; i++) {
        float4 o;
        o.x = acc[i][0] + bv.x;
        o.y = acc[i][1] + bv.y;
        o.z = acc[i][2] + bv.z;
        o.w = acc[i][3] + bv.w;
        *(float4*)(out + (row0 + rg * 4 + i) * CDIM + cg * 4) = o;
    }
}

// ---------------- launch ----------------
extern "C" void kernel_launch(void* const* d_in, const int* in_sizes, int n_in,
                              void* d_out, int out_size)
{
    (void)in_sizes; (void)n_in; (void)out_size;
    const float* x       = (const float*)d_in[0];
    const float* snr     = (const float*)d_in[1];
    const float* norm_w  = (const float*)d_in[2];
    const float* norm_b  = (const float*)d_in[3];
    const float* sm0_w   = (const float*)d_in[4];
    const float* sm0_b   = (const float*)d_in[5];
    const float* smm_w   = (const float*)d_in[6];
    const float* smm_b   = (const float*)d_in[7];
    const float* sml_w   = (const float*)d_in[8];
    const float* sml_b   = (const float*)d_in[9];
    const float* bm_w1   = (const float*)d_in[10];
    const float* bm_b1   = (const float*)d_in[11];
    const float* bm_w2   = (const float*)d_in[12];
    const float* bm_b2   = (const float*)d_in[13];
    const float* bm_w3   = (const float*)d_in[14];
    const float* bm_b3   = (const float*)d_in[15];
    const float* head_w  = (const float*)d_in[16];
    const float* head_b  = (const float*)d_in[17];

    float *p_mat, *p_ct, *p_xnf, *p_xgf;
    __nv_bfloat16 *p_wtb, *p_xnb;
    cudaGetSymbolAddress((void**)&p_mat, g_mat);
    cudaGetSymbolAddress((void**)&p_ct,  g_ct);
    cudaGetSymbolAddress((void**)&p_wtb, g_wtb);
    cudaGetSymbolAddress((void**)&p_xnf, g_xnf);
    cudaGetSymbolAddress((void**)&p_xnb, g_xnb);
    cudaGetSymbolAddress((void**)&p_xgf, g_xgf);

    constexpr int SMEM_G = STAGES * (BM_T + 160) * LDT * 2;  // 92160 B
    cudaFuncSetAttribute(gemm_k<160>, cudaFuncAttributeMaxDynamicSharedMemorySize, SMEM_G);

    // ---- token-independent precompute ----
    bm_kernel<<<NLAYER, 512>>>(snr, bm_w1, bm_b1, bm_w2, bm_b2, bm_w3, bm_b3);
    materialize_kernel<<<1024, 256>>>(sm0_w, sm0_b, smm_w, smm_b, sml_w, sml_b);

    // LayerNorm of tokens
    ln_kernel<<<MTOK/8, 256>>>(x, norm_w, norm_b);

    // ---- balanced-tree composition of 8 augmented matrices ----
    // L1 (z=4): slot(8+z) = slot(2z) @ slot(2z+1)
    mm3<<<dim3(ADIM/32, ADIM/32, 4), 256>>>(p_mat + 0*MS, 2*MS, p_mat + 1*MS, 2*MS, p_mat + 8*MS, MS);
    // L2 (z=2): slot(12+z) = slot(8+2z) @ slot(9+2z)
    mm3<<<dim3(ADIM/32, ADIM/32, 2), 256>>>(p_mat + 8*MS, 2*MS, p_mat + 9*MS, 2*MS, p_mat + 12*MS, MS);
    // L3 (z=1): slot14 = slot12 @ slot13
    mm3<<<dim3(ADIM/32, ADIM/32, 1), 256>>>(p_mat + 12*MS, 0, p_mat + 13*MS, 0, p_mat + 14*MS, 0);
    extract_kernel<<<160, 256>>>();

    // ---- token compute: ONE fused E->E GEMM, then head ----
    gemm_k<160><<<dim3(MTOK/BM_T, EDIM/160), 512, SMEM_G>>>(
        p_xnb, p_wtb, p_ct, p_xnf, p_xgf, MTOK, EDIM, EDIM);
    head_kernel<<<MTOK/128, 256>>>(p_xgf, head_w, head_b, (float*)d_out);
}

// round 13
// speedup vs baseline: 10.7569x; 1.0345x over previous
#include <cuda_runtime.h>
#include <cuda_bf16.h>
#include <cstdint>

// ---------------- problem constants ----------------
#define BATCH 64
#define LSEQ  1024
#define EDIM  320
#define HDIM  480
#define CDIM  32
#define NLAYER 7
#define MTOK  (BATCH*LSEQ)   // 65536
#define ADIM  512            // augmented matrix size (481 used, padded)
#define MS    (ADIM*ADIM)    // elements per slot

// ---------------- device scratch ----------------
__device__ float          g_bm[NLAYER*HDIM];
// slots 0..7: inputs (Wl~,A6~,A5~,A4~,A3~,A2~,A1~,M0~); 8..11 L1; 12..13 L2; 14 final
__device__ float          g_mat[15*MS];
__device__ float          g_ct[EDIM];
__device__ __nv_bfloat16  g_wtb[EDIM*EDIM];
__device__ float          g_xnf[(size_t)MTOK*EDIM];
__device__ __nv_bfloat16  g_xnb[(size_t)MTOK*EDIM];
__device__ float          g_xgf[(size_t)MTOK*EDIM];

// ---------------- bm: one CTA per layer, warp-per-row coalesced ----------------
__global__ __launch_bounds__(512) void bm_kernel(
    const float* __restrict__ snr,
    const float* __restrict__ w1, const float* __restrict__ b1,
    const float* __restrict__ w2, const float* __restrict__ b2,
    const float* __restrict__ w3, const float* __restrict__ b3)
{
    const int i = blockIdx.x;
    __shared__ float h1[HDIM];
    __shared__ float h2[HDIM];
    const int tid  = threadIdx.x;
    const int warp = tid >> 5;
    const int lane = tid & 31;
    const float s = snr[0];

    for (int j = tid; j < HDIM; j += 512)
        h1[j] = fmaxf(0.f, s * w1[i*HDIM + j] + b1[i*HDIM + j]);
    __syncthreads();

    for (int j = warp; j < HDIM; j += 16) {
        const float* w = w2 + ((size_t)i*HDIM + j) * HDIM;
        float acc = 0.f;
        for (int k = lane; k < HDIM; k += 32) acc += w[k] * h1[k];
        #pragma unroll
        for (int o = 16; o > 0; o >>= 1) acc += __shfl_xor_sync(0xffffffffu, acc, o);
        if (lane == 0) h2[j] = fmaxf(0.f, acc + b2[i*HDIM + j]);
    }
    __syncthreads();

    for (int j = warp; j < HDIM; j += 16) {
        const float* w = w3 + ((size_t)i*HDIM + j) * HDIM;
        float acc = 0.f;
        for (int k = lane; k < HDIM; k += 32) acc += w[k] * h2[k];
        #pragma unroll
        for (int o = 16; o > 0; o >>= 1) acc += __shfl_xor_sync(0xffffffffu, acc, o);
        if (lane == 0) g_bm[i*HDIM + j] = 1.f / (1.f + expf(-(acc + b3[i*HDIM + j])));
    }
}

// ---------------- materialize the 8 augmented matrices ----------------
__global__ void materialize_kernel(
    const float* __restrict__ sm0_w, const float* __restrict__ sm0_b,
    const float* __restrict__ smm_w, const float* __restrict__ smm_b,
    const float* __restrict__ sml_w, const float* __restrict__ sml_b)
{
    const long stride = (long)gridDim.x * blockDim.x;
    for (long idx = (long)blockIdx.x * blockDim.x + threadIdx.x; idx < 8L*MS; idx += stride) {
        const int slot = (int)(idx / MS);
        const int e = (int)(idx - (long)slot * MS);
        const int r = e >> 9;
        const int c = e & 511;
        float v = 0.f;
        if (slot == 0) {               // Wl~
            if (r < EDIM) {
                if (c < HDIM)       v = sml_w[r*HDIM + c];
                else if (c == HDIM) v = sml_b[r];
            } else if (r == EDIM && c == HDIM) v = 1.f;
        } else if (slot <= 6) {        // A_i~, i = 7-slot
            const int i = 7 - slot;
            if (r < HDIM) {
                const float g = g_bm[i*HDIM + r];
                if (c < HDIM)       v = g * smm_w[((size_t)(i-1)*HDIM + r)*HDIM + c];
                else if (c == HDIM) v = g * smm_b[(i-1)*HDIM + r];
            } else if (r == HDIM && c == HDIM) v = 1.f;
        } else {                       // M0~
            if (r < HDIM) {
                const float g = g_bm[r];
                if (c < EDIM)       v = g * sm0_w[r*EDIM + c];
                else if (c == EDIM) v = g * sm0_b[r];
            } else if (r == HDIM && c == EDIM) v = 1.f;
        }
        g_mat[idx] = v;
    }
}

// ---------------- batched 512x512x512 fp32 GEMM: C = A @ B ----------------
// 64x64 tile, 256 threads = 16x16, 4x4 per thread, K-chunk 32, double-buffered.
// A staged transposed [k][m] so inner loop is LDS.128 for both operands.
#define TKK 32
__global__ __launch_bounds__(256) void mm3(
    const float* __restrict__ Ab, int Asz,
    const float* __restrict__ Bb, int Bsz,
    float* __restrict__ Cb, int Csz)
{
    const float* A = Ab + (size_t)blockIdx.z * Asz;
    const float* B = Bb + (size_t)blockIdx.z * Bsz;
    float*       C = Cb + (size_t)blockIdx.z * Csz;

    __shared__ float As[2][TKK][68];   // [k][m]
    __shared__ float Bs[2][TKK][68];   // [k][n]
    const int tid = threadIdx.x;
    const int tx = tid & 15;           // n group (4 cols)
    const int ty = tid >> 4;           // m group (4 rows)
    const int r0 = blockIdx.y * 64, c0 = blockIdx.x * 64;

    const int am = tid >> 3;           // 0..31 (+32 for second quad)
    const int ak = (tid & 7) * 4;      // 0..28
    const int bk = tid >> 4;           // 0..15 (+16 for second)
    const int bn = (tid & 15) * 4;     // 0..60

    float4 fa0, fa1, fb0, fb1;
    auto fetch = [&](int kt) {
        fa0 = *(const float4*)(A + (size_t)(r0 + am)      * ADIM + kt*TKK + ak);
        fa1 = *(const float4*)(A + (size_t)(r0 + am + 32) * ADIM + kt*TKK + ak);
        fb0 = *(const float4*)(B + (size_t)(kt*TKK + bk)      * ADIM + c0 + bn);
        fb1 = *(const float4*)(B + (size_t)(kt*TKK + bk + 16) * ADIM + c0 + bn);
    };
    auto store = [&](int buf) {
        As[buf][ak+0][am] = fa0.x; As[buf][ak+1][am] = fa0.y;
        As[buf][ak+2][am] = fa0.z; As[buf][ak+3][am] = fa0.w;
        As[buf][ak+0][am+32] = fa1.x; As[buf][ak+1][am+32] = fa1.y;
        As[buf][ak+2][am+32] = fa1.z; As[buf][ak+3][am+32] = fa1.w;
        *(float4*)&Bs[buf][bk][bn]      = fb0;
        *(float4*)&Bs[buf][bk+16][bn]   = fb1;
    };

    fetch(0);
    store(0);
    __syncthreads();

    float acc[4][4];
    #pragma unroll
    for (int i = 0; i < 4; i++)
        #pragma unroll
        for (int j = 0; j < 4; j++) acc[i][j] = 0.f;

    const int KT = ADIM / TKK;         // 16
    for (int kt = 0; kt < KT; kt++) {
        const int cur = kt & 1;
        if (kt + 1 < KT) fetch(kt + 1);
        #pragma unroll
        for (int k = 0; k < TKK; k++) {
            const float4 av = *(const float4*)&As[cur][k][ty*4];
            const float4 bv = *(const float4*)&Bs[cur][k][tx*4];
            acc[0][0] += av.x*bv.x; acc[0][1] += av.x*bv.y; acc[0][2] += av.x*bv.z; acc[0][3] += av.x*bv.w;
            acc[1][0] += av.y*bv.x; acc[1][1] += av.y*bv.y; acc[1][2] += av.y*bv.z; acc[1][3] += av.y*bv.w;
            acc[2][0] += av.z*bv.x; acc[2][1] += av.z*bv.y; acc[2][2] += av.z*bv.z; acc[2][3] += av.z*bv.w;
            acc[3][0] += av.w*bv.x; acc[3][1] += av.w*bv.y; acc[3][2] += av.w*bv.z; acc[3][3] += av.w*bv.w;
        }
        if (kt + 1 < KT) {
            __syncthreads();
            store(cur ^ 1);
            __syncthreads();
        }
    }

    #pragma unroll
    for (int i = 0; i < 4; i++) {
        float4 o;
        o.x = acc[i][0]; o.y = acc[i][1]; o.z = acc[i][2]; o.w = acc[i][3];
        *(float4*)(C + (size_t)(r0 + ty*4 + i) * ADIM + c0 + tx*4) = o;
    }
}

// extract bf16 weight + bias column from final composite (slot 14)
__global__ void extract_kernel()
{
    const float* T = g_mat + 14*MS;
    const int stride = gridDim.x * blockDim.x;
    const int idx0 = blockIdx.x * blockDim.x + threadIdx.x;
    for (int i = idx0; i < EDIM*EDIM; i += stride) {
        const int r = i / EDIM, c = i - r * EDIM;
        g_wtb[i] = __float2bfloat16(T[(size_t)r * ADIM + c]);
    }
    if (idx0 < EDIM) g_ct[idx0] = T[(size_t)idx0 * ADIM + EDIM];
}

// LayerNorm: one warp per token. fp32 + bf16 copies.
__global__ void ln_kernel(const float* __restrict__ x,
                          const float* __restrict__ w, const float* __restrict__ b)
{
    const int warp = threadIdx.x >> 5;
    const int lane = threadIdx.x & 31;
    const size_t t = (size_t)blockIdx.x * 8 + warp;
    const float* xp = x + t * EDIM;
    float v[10];
    float s = 0.f, s2 = 0.f;
    #pragma unroll
    for (int i = 0; i < 10; i++) {
        v[i] = xp[lane + 32*i];
        s  += v[i];
        s2 += v[i]*v[i];
    }
    #pragma unroll
    for (int o = 16; o > 0; o >>= 1) {
        s  += __shfl_xor_sync(0xffffffffu, s,  o);
        s2 += __shfl_xor_sync(0xffffffffu, s2, o);
    }
    const float mu  = s  * (1.f/EDIM);
    const float var = s2 * (1.f/EDIM) - mu*mu;
    const float inv = 1.f / sqrtf(var + 1e-5f);
    #pragma unroll
    for (int i = 0; i < 10; i++) {
        const int c = lane + 32*i;
        const float y = (v[i] - mu) * inv * w[c] + b[c];
        g_xnf[t*EDIM + c] = y;
        g_xnb[t*EDIM + c] = __float2bfloat16(y);
    }
}

// ---------------- GEMM: C = sigmoid(A @ W^T + ct) * xn -> fp32 ----------------
#define BM_T 128
#define BK_T 32
#define LDT  (BK_T + 8)
#define STAGES 5

__device__ __forceinline__ void cp16(uint32_t s, const void* g) {
    asm volatile("cp.async.cg.shared.global [%0], [%1], 16;" :: "r"(s), "l"(g));
}
__device__ __forceinline__ void ldm4(uint32_t a, uint32_t& r0, uint32_t& r1, uint32_t& r2, uint32_t& r3) {
    asm volatile("ldmatrix.sync.aligned.m8n8.x4.shared.b16 {%0,%1,%2,%3}, [%4];"
                 : "=r"(r0), "=r"(r1), "=r"(r2), "=r"(r3) : "r"(a));
}
__device__ __forceinline__ void ldm2(uint32_t a, uint32_t& r0, uint32_t& r1) {
    asm volatile("ldmatrix.sync.aligned.m8n8.x2.shared.b16 {%0,%1}, [%2];"
                 : "=r"(r0), "=r"(r1) : "r"(a));
}
__device__ __forceinline__ void mma16816(float* c, const uint32_t* a, const uint32_t* b) {
    asm volatile("mma.sync.aligned.m16n8k16.row.col.f32.bf16.bf16.f32 "
                 "{%0,%1,%2,%3}, {%4,%5,%6,%7}, {%8,%9}, {%0,%1,%2,%3};"
                 : "+f"(c[0]), "+f"(c[1]), "+f"(c[2]), "+f"(c[3])
                 : "r"(a[0]), "r"(a[1]), "r"(a[2]), "r"(a[3]), "r"(b[0]), "r"(b[1]));
}

template<int BN>
__global__ __launch_bounds__(512, 1) void gemm_k(
    const __nv_bfloat16* __restrict__ A, const __nv_bfloat16* __restrict__ W,
    const float* __restrict__ bias, const float* __restrict__ xnf,
    float* __restrict__ Cout, int M, int N, int K)
{
    constexpr int NIW  = BN / 32;
    constexpr int ASTG = BM_T * LDT;
    constexpr int BSTG = BN * LDT;

    extern __shared__ __align__(16) __nv_bfloat16 smem[];
    __nv_bfloat16* Asm = smem;
    __nv_bfloat16* Bsm = smem + STAGES * ASTG;

    const int tid  = threadIdx.x;
    const int lane = tid & 31;
    const int warp = tid >> 5;
    const int wr = warp & 3;
    const int wc = warp >> 2;

    const uint32_t sA = (uint32_t)__cvta_generic_to_shared(Asm);
    const uint32_t sB = (uint32_t)__cvta_generic_to_shared(Bsm);
    const size_t Arow0 = (size_t)blockIdx.x * BM_T;
    const size_t Brow0 = (size_t)blockIdx.y * BN;
    const int KT = K / BK_T;

    auto load_st = [&](int kt, int buf) {
        const __nv_bfloat16* Ag = A + Arow0 * K + (size_t)kt * BK_T;
        const uint32_t sa = sA + buf * (ASTG * 2);
        for (int id = tid; id < BM_T * 4; id += 512) {
            const int r = id >> 2, c = (id & 3) * 8;
            cp16(sa + (r * LDT + c) * 2, Ag + (size_t)r * K + c);
        }
        const __nv_bfloat16* Bg = W + Brow0 * K + (size_t)kt * BK_T;
        const uint32_t sb = sB + buf * (BSTG * 2);
        for (int id = tid; id < BN * 4; id += 512) {
            const int r = id >> 2, c = (id & 3) * 8;
            cp16(sb + (r * LDT + c) * 2, Bg + (size_t)r * K + c);
        }
        asm volatile("cp.async.commit_group;");
    };

    float acc[2][NIW][4];
    #pragma unroll
    for (int mi = 0; mi < 2; mi++)
        #pragma unroll
        for (int ni = 0; ni < NIW; ni++)
            #pragma unroll
            for (int e = 0; e < 4; e++) acc[mi][ni][e] = 0.f;

    // prologue: 4 stages in flight
    load_st(0, 0);
    load_st(1, 1);
    load_st(2, 2);
    load_st(3, 3);

    for (int kt = 0; kt < KT; kt++) {
        const int rem = KT - 1 - kt;
        if (rem >= 3)      asm volatile("cp.async.wait_group 3;");
        else if (rem == 2) asm volatile("cp.async.wait_group 2;");
        else if (rem == 1) asm volatile("cp.async.wait_group 1;");
        else               asm volatile("cp.async.wait_group 0;");
        __syncthreads();

        if (kt + 4 < KT) load_st(kt + 4, (kt + 4) % STAGES);

        const int buf = kt % STAGES;
        const uint32_t baseA = sA + buf * (ASTG * 2);
        const uint32_t baseB = sB + buf * (BSTG * 2);
        #pragma unroll
        for (int ks = 0; ks < 2; ks++) {
            uint32_t af[2][4];
            #pragma unroll
            for (int mi = 0; mi < 2; mi++) {
                const int row = wr * 32 + mi * 16 + (lane & 15);
                const int col = ks * 16 + (lane >> 4) * 8;
                ldm4(baseA + (row * LDT + col) * 2, af[mi][0], af[mi][1], af[mi][2], af[mi][3]);
            }
            uint32_t bf[NIW][2];
            #pragma unroll
            for (int np = 0; np < NIW / 2; np++) {
                const int row = wc * (BN / 4) + np * 16 + (lane & 7) + ((lane >> 4) << 3);
                const int col = ks * 16 + (((lane >> 3) & 1) << 3);
                ldm4(baseB + (row * LDT + col) * 2,
                     bf[2*np][0], bf[2*np][1], bf[2*np+1][0], bf[2*np+1][1]);
            }
            if (NIW & 1) {
                const int l = lane & 15;
                const int row = wc * (BN / 4) + (NIW - 1) * 8 + (l & 7);
                const int col = ks * 16 + ((l >> 3) << 3);
                ldm2(baseB + (row * LDT + col) * 2, bf[NIW-1][0], bf[NIW-1][1]);
            }
            #pragma unroll
            for (int mi = 0; mi < 2; mi++)
                #pragma unroll
                for (int ni = 0; ni < NIW; ni++)
                    mma16816(acc[mi][ni], af[mi], bf[ni]);
        }
    }

    const size_t mb = Arow0 + wr * 32;
    const int nb = (int)Brow0 + wc * (BN / 4);
    #pragma unroll
    for (int mi = 0; mi < 2; mi++) {
        #pragma unroll
        for (int ni = 0; ni < NIW; ni++) {
            const size_t m0 = mb + mi * 16 + (lane >> 2);
            const int n0 = nb + ni * 8 + (lane & 3) * 2;
            #pragma unroll
            for (int e = 0; e < 4; e++) {
                const size_t m = m0 + ((e >= 2) ? 8 : 0);
                const int n = n0 + (e & 1);
                const float v = acc[mi][ni][e] + bias[n];
                const float sg = 1.f / (1.f + __expf(-v));
                Cout[m * N + n] = sg * xnf[m * N + n];
            }
        }
    }
}

// ---------------- head GEMM: fp32, M=65536 N=32 K=320 ----------------
__global__ __launch_bounds__(256, 2) void head_kernel(
    const float* __restrict__ A, const float* __restrict__ W,
    const float* __restrict__ bias, float* __restrict__ out)
{
    __shared__ float ws[EDIM * CDIM];
    __shared__ float as[32 * 128];

    const int tid = threadIdx.x;
    for (int i = tid; i < EDIM * CDIM; i += 256) {
        const int c = i & 31;
        const int k = i >> 5;
        ws[k * CDIM + c] = W[c * EDIM + k];
    }

    const size_t row0 = (size_t)blockIdx.x * 128;
    const int rg = tid >> 3;
    const int cg = tid & 7;

    float acc[4][4];
    #pragma unroll
    for (int i = 0; i < 4; i++)
        #pragma unroll
        for (int j = 0; j < 4; j++) acc[i][j] = 0.f;

    for (int k0 = 0; k0 < EDIM; k0 += 32) {
        __syncthreads();
        #pragma unroll
        for (int i = 0; i < 4; i++) {
            const int idx = tid + 256 * i;
            const int r  = idx & 127;
            const int kq = idx >> 7;
            const float4 v = *(const float4*)(A + (row0 + r) * EDIM + k0 + kq * 4);
            as[(kq * 4 + 0) * 128 + r] = v.x;
            as[(kq * 4 + 1) * 128 + r] = v.y;
            as[(kq * 4 + 2) * 128 + r] = v.z;
            as[(kq * 4 + 3) * 128 + r] = v.w;
        }
        __syncthreads();
        #pragma unroll
        for (int k = 0; k < 32; k++) {
            const float4 av = *(const float4*)(as + k * 128 + rg * 4);
            const float4 bv = *(const float4*)(ws + (k0 + k) * CDIM + cg * 4);
            acc[0][0] += av.x * bv.x; acc[0][1] += av.x * bv.y;
            acc[0][2] += av.x * bv.z; acc[0][3] += av.x * bv.w;
            acc[1][0] += av.y * bv.x; acc[1][1] += av.y * bv.y;
            acc[1][2] += av.y * bv.z; acc[1][3] += av.y * bv.w;
            acc[2][0] += av.z * bv.x; acc[2][1] += av.z * bv.y;
            acc[2][2] += av.z * bv.z; acc[2][3] += av.z * bv.w;
            acc[3][0] += av.w * bv.x; acc[3][1] += av.w * bv.y;
            acc[3][2] += av.w * bv.z; acc[3][3] += av.w * bv.w;
        }
    }

    const float4 bv = *(const float4*)(bias + cg * 4);
    #pragma unroll
    for (int i = 0; i < 4; i++) {
        float4 o;
        o.x = acc[i][0] + bv.x;
        o.y = acc[i][1] + bv.y;
        o.z = acc[i][2] + bv.z;
        o.w = acc[i][3] + bv.w;
        *(float4*)(out + (row0 + rg * 4 + i) * CDIM + cg * 4) = o;
    }
}

// ---------------- launch ----------------
extern "C" void kernel_launch(void* const* d_in, const int* in_sizes, int n_in,
                              void* d_out, int out_size)
{
    (void)in_sizes; (void)n_in; (void)out_size;
    const float* x       = (const float*)d_in[0];
    const float* snr     = (const float*)d_in[1];
    const float* norm_w  = (const float*)d_in[2];
    const float* norm_b  = (const float*)d_in[3];
    const float* sm0_w   = (const float*)d_in[4];
    const float* sm0_b   = (const float*)d_in[5];
    const float* smm_w   = (const float*)d_in[6];
    const float* smm_b   = (const float*)d_in[7];
    const float* sml_w   = (const float*)d_in[8];
    const float* sml_b   = (const float*)d_in[9];
    const float* bm_w1   = (const float*)d_in[10];
    const float* bm_b1   = (const float*)d_in[11];
    const float* bm_w2   = (const float*)d_in[12];
    const float* bm_b2   = (const float*)d_in[13];
    const float* bm_w3   = (const float*)d_in[14];
    const float* bm_b3   = (const float*)d_in[15];
    const float* head_w  = (const float*)d_in[16];
    const float* head_b  = (const float*)d_in[17];

    float *p_mat, *p_ct, *p_xnf, *p_xgf;
    __nv_bfloat16 *p_wtb, *p_xnb;
    cudaGetSymbolAddress((void**)&p_mat, g_mat);
    cudaGetSymbolAddress((void**)&p_ct,  g_ct);
    cudaGetSymbolAddress((void**)&p_wtb, g_wtb);
    cudaGetSymbolAddress((void**)&p_xnf, g_xnf);
    cudaGetSymbolAddress((void**)&p_xnb, g_xnb);
    cudaGetSymbolAddress((void**)&p_xgf, g_xgf);

    constexpr int SMEM_G = STAGES * (BM_T + 160) * LDT * 2;  // 115200 B
    cudaFuncSetAttribute(gemm_k<160>, cudaFuncAttributeMaxDynamicSharedMemorySize, SMEM_G);

    // ---- token-independent precompute ----
    bm_kernel<<<NLAYER, 512>>>(snr, bm_w1, bm_b1, bm_w2, bm_b2, bm_w3, bm_b3);
    materialize_kernel<<<1024, 256>>>(sm0_w, sm0_b, smm_w, smm_b, sml_w, sml_b);

    // LayerNorm of tokens
    ln_kernel<<<MTOK/8, 256>>>(x, norm_w, norm_b);

    // ---- balanced-tree composition of 8 augmented matrices ----
    mm3<<<dim3(ADIM/64, ADIM/64, 4), 256>>>(p_mat + 0*MS, 2*MS, p_mat + 1*MS, 2*MS, p_mat + 8*MS, MS);
    mm3<<<dim3(ADIM/64, ADIM/64, 2), 256>>>(p_mat + 8*MS, 2*MS, p_mat + 9*MS, 2*MS, p_mat + 12*MS, MS);
    mm3<<<dim3(ADIM/64, ADIM/64, 1), 256>>>(p_mat + 12*MS, 0, p_mat + 13*MS, 0, p_mat + 14*MS, 0);
    extract_kernel<<<160, 256>>>();

    // ---- token compute: ONE fused E->E GEMM, then head ----
    gemm_k<160><<<dim3(MTOK/BM_T, EDIM/160), 512, SMEM_G>>>(
        p_xnb, p_wtb, p_ct, p_xnf, p_xgf, MTOK, EDIM, EDIM);
    head_kernel<<<MTOK/128, 256>>>(p_xgf, head_w, head_b, (float*)d_out);
}

// round 14
// speedup vs baseline: 11.2852x; 1.0491x over previous
#include <cuda_runtime.h>
#include <cuda_bf16.h>
#include <cstdint>

// ---------------- problem constants ----------------
#define BATCH 64
#define LSEQ  1024
#define EDIM  320
#define HDIM  480
#define CDIM  32
#define NLAYER 7
#define MTOK  (BATCH*LSEQ)   // 65536
#define ADIM  512            // augmented matrix size (481 used, padded)
#define MS    (ADIM*ADIM)    // elements per slot

// ---------------- device scratch ----------------
__device__ float          g_bm[NLAYER*HDIM];
// slots 0..7: inputs (Wl~,A6~,A5~,A4~,A3~,A2~,A1~,M0~); 8..11 L1; 12..13 L2
__device__ __align__(1024) float g_mat[14*MS];
__device__ float          g_ct[EDIM];
__device__ __nv_bfloat16  g_wtb[EDIM*EDIM];
__device__ float          g_xnf[(size_t)MTOK*EDIM];
__device__ __nv_bfloat16  g_xnb[(size_t)MTOK*EDIM];
__device__ float          g_xgf[(size_t)MTOK*EDIM];

__device__ __forceinline__ void cp16(uint32_t s, const void* g) {
    asm volatile("cp.async.cg.shared.global [%0], [%1], 16;" :: "r"(s), "l"(g));
}

// ---------------- bm: one CTA per layer, warp-per-row coalesced ----------------
__global__ __launch_bounds__(512) void bm_kernel(
    const float* __restrict__ snr,
    const float* __restrict__ w1, const float* __restrict__ b1,
    const float* __restrict__ w2, const float* __restrict__ b2,
    const float* __restrict__ w3, const float* __restrict__ b3)
{
    const int i = blockIdx.x;
    __shared__ float h1[HDIM];
    __shared__ float h2[HDIM];
    const int tid  = threadIdx.x;
    const int warp = tid >> 5;
    const int lane = tid & 31;
    const float s = snr[0];

    for (int j = tid; j < HDIM; j += 512)
        h1[j] = fmaxf(0.f, s * w1[i*HDIM + j] + b1[i*HDIM + j]);
    __syncthreads();

    for (int j = warp; j < HDIM; j += 16) {
        const float* w = w2 + ((size_t)i*HDIM + j) * HDIM;
        float acc = 0.f;
        for (int k = lane; k < HDIM; k += 32) acc += w[k] * h1[k];
        #pragma unroll
        for (int o = 16; o > 0; o >>= 1) acc += __shfl_xor_sync(0xffffffffu, acc, o);
        if (lane == 0) h2[j] = fmaxf(0.f, acc + b2[i*HDIM + j]);
    }
    __syncthreads();

    for (int j = warp; j < HDIM; j += 16) {
        const float* w = w3 + ((size_t)i*HDIM + j) * HDIM;
        float acc = 0.f;
        for (int k = lane; k < HDIM; k += 32) acc += w[k] * h2[k];
        #pragma unroll
        for (int o = 16; o > 0; o >>= 1) acc += __shfl_xor_sync(0xffffffffu, acc, o);
        if (lane == 0) g_bm[i*HDIM + j] = 1.f / (1.f + expf(-(acc + b3[i*HDIM + j])));
    }
}

// ---------------- materialize the 8 augmented matrices ----------------
__global__ void materialize_kernel(
    const float* __restrict__ sm0_w, const float* __restrict__ sm0_b,
    const float* __restrict__ smm_w, const float* __restrict__ smm_b,
    const float* __restrict__ sml_w, const float* __restrict__ sml_b)
{
    const long stride = (long)gridDim.x * blockDim.x;
    for (long idx = (long)blockIdx.x * blockDim.x + threadIdx.x; idx < 8L*MS; idx += stride) {
        const int slot = (int)(idx / MS);
        const int e = (int)(idx - (long)slot * MS);
        const int r = e >> 9;
        const int c = e & 511;
        float v = 0.f;
        if (slot == 0) {               // Wl~
            if (r < EDIM) {
                if (c < HDIM)       v = sml_w[r*HDIM + c];
                else if (c == HDIM) v = sml_b[r];
            } else if (r == EDIM && c == HDIM) v = 1.f;
        } else if (slot <= 6) {        // A_i~, i = 7-slot
            const int i = 7 - slot;
            if (r < HDIM) {
                const float g = g_bm[i*HDIM + r];
                if (c < HDIM)       v = g * smm_w[((size_t)(i-1)*HDIM + r)*HDIM + c];
                else if (c == HDIM) v = g * smm_b[(i-1)*HDIM + r];
            } else if (r == HDIM && c == HDIM) v = 1.f;
        } else {                       // M0~
            if (r < HDIM) {
                const float g = g_bm[r];
                if (c < EDIM)       v = g * sm0_w[r*EDIM + c];
                else if (c == EDIM) v = g * sm0_b[r];
            } else if (r == HDIM && c == EDIM) v = 1.f;
        }
        g_mat[idx] = v;
    }
}

// ---------------- batched 512x512x512 fp32 GEMM: C = A @ B ----------------
// 64x64 tile, 256 threads (16x16), 4x4 per thread, BK=32, cp.async 4-stage ring.
// A staged row-major [m][k] (36-stride), B [k][n] (68-stride).
// FIN=1: instead of writing C, write g_wtb (bf16) + g_ct from the 321x321 result.
#define MM_STG 4
template<int FIN>
__global__ __launch_bounds__(256) void mm3(
    const float* __restrict__ Ab, int Asz,
    const float* __restrict__ Bb, int Bsz,
    float* __restrict__ Cb, int Csz)
{
    const float* A = Ab + (size_t)blockIdx.z * Asz;
    const float* B = Bb + (size_t)blockIdx.z * Bsz;
    float*       C = Cb + (size_t)blockIdx.z * Csz;

    __shared__ __align__(16) float As[MM_STG][64][36];
    __shared__ __align__(16) float Bs[MM_STG][32][68];

    const int tid = threadIdx.x;
    const int tx = tid & 15;           // n group (4 cols)
    const int ty = tid >> 4;           // m group (4 rows)
    const int r0 = blockIdx.y * 64, c0 = blockIdx.x * 64;

    const uint32_t sA = (uint32_t)__cvta_generic_to_shared(&As[0][0][0]);
    const uint32_t sB = (uint32_t)__cvta_generic_to_shared(&Bs[0][0][0]);

    auto load_st = [&](int kt, int buf) {
        // A: 512 cp16 -> 2/thread ; row = id>>3, kq = (id&7)*4
        #pragma unroll
        for (int id = tid; id < 512; id += 256) {
            const int row = id >> 3, kc = (id & 7) * 4;
            cp16(sA + ((buf*64 + row)*36 + kc)*4,
                 A + (size_t)(r0 + row) * ADIM + kt*32 + kc);
        }
        // B: 512 cp16 ; row = id>>4, nq = (id&15)*4
        #pragma unroll
        for (int id = tid; id < 512; id += 256) {
            const int row = id >> 4, nc = (id & 15) * 4;
            cp16(sB + ((buf*32 + row)*68 + nc)*4,
                 B + (size_t)(kt*32 + row) * ADIM + c0 + nc);
        }
        asm volatile("cp.async.commit_group;");
    };

    float acc[4][4];
    #pragma unroll
    for (int i = 0; i < 4; i++)
        #pragma unroll
        for (int j = 0; j < 4; j++) acc[i][j] = 0.f;

    load_st(0, 0);
    load_st(1, 1);
    load_st(2, 2);

    const int KT = ADIM / 32;          // 16
    for (int kt = 0; kt < KT; kt++) {
        const int rem = KT - 1 - kt;
        if (rem >= 2)      asm volatile("cp.async.wait_group 2;");
        else if (rem == 1) asm volatile("cp.async.wait_group 1;");
        else               asm volatile("cp.async.wait_group 0;");
        __syncthreads();

        if (kt + 3 < KT) load_st(kt + 3, (kt + 3) & 3);

        const int buf = kt & 3;
        #pragma unroll
        for (int k = 0; k < 32; k++) {
            const float4 bv = *(const float4*)&Bs[buf][k][tx*4];
            const float a0 = As[buf][ty*4+0][k];
            const float a1 = As[buf][ty*4+1][k];
            const float a2 = As[buf][ty*4+2][k];
            const float a3 = As[buf][ty*4+3][k];
            acc[0][0] += a0*bv.x; acc[0][1] += a0*bv.y; acc[0][2] += a0*bv.z; acc[0][3] += a0*bv.w;
            acc[1][0] += a1*bv.x; acc[1][1] += a1*bv.y; acc[1][2] += a1*bv.z; acc[1][3] += a1*bv.w;
            acc[2][0] += a2*bv.x; acc[2][1] += a2*bv.y; acc[2][2] += a2*bv.z; acc[2][3] += a2*bv.w;
            acc[3][0] += a3*bv.x; acc[3][1] += a3*bv.y; acc[3][2] += a3*bv.z; acc[3][3] += a3*bv.w;
        }
        __syncthreads();
    }

    if (FIN == 0) {
        #pragma unroll
        for (int i = 0; i < 4; i++) {
            float4 o;
            o.x = acc[i][0]; o.y = acc[i][1]; o.z = acc[i][2]; o.w = acc[i][3];
            *(float4*)(C + (size_t)(r0 + ty*4 + i) * ADIM + c0 + tx*4) = o;
        }
    } else {
        // final composite: top-left 320x320 -> g_wtb (bf16), col 320 -> g_ct
        const int c = c0 + tx*4;
        #pragma unroll
        for (int i = 0; i < 4; i++) {
            const int r = r0 + ty*4 + i;
            if (r < EDIM) {
                if (c + 3 < EDIM) {
                    __nv_bfloat162 h0 = __floats2bfloat162_rn(acc[i][0], acc[i][1]);
                    __nv_bfloat162 h1 = __floats2bfloat162_rn(acc[i][2], acc[i][3]);
                    uint2 pk;
                    pk.x = *(const uint32_t*)&h0;
                    pk.y = *(const uint32_t*)&h1;
                    *(uint2*)(&g_wtb[(size_t)r * EDIM + c]) = pk;
                } else if (c == EDIM) {
                    g_ct[r] = acc[i][0];
                }
            }
        }
    }
}

// LayerNorm: one warp per token. fp32 + bf16 copies.
__global__ void ln_kernel(const float* __restrict__ x,
                          const float* __restrict__ w, const float* __restrict__ b)
{
    const int warp = threadIdx.x >> 5;
    const int lane = threadIdx.x & 31;
    const size_t t = (size_t)blockIdx.x * 8 + warp;
    const float* xp = x + t * EDIM;
    float v[10];
    float s = 0.f, s2 = 0.f;
    #pragma unroll
    for (int i = 0; i < 10; i++) {
        v[i] = xp[lane + 32*i];
        s  += v[i];
        s2 += v[i]*v[i];
    }
    #pragma unroll
    for (int o = 16; o > 0; o >>= 1) {
        s  += __shfl_xor_sync(0xffffffffu, s,  o);
        s2 += __shfl_xor_sync(0xffffffffu, s2, o);
    }
    const float mu  = s  * (1.f/EDIM);
    const float var = s2 * (1.f/EDIM) - mu*mu;
    const float inv = 1.f / sqrtf(var + 1e-5f);
    #pragma unroll
    for (int i = 0; i < 10; i++) {
        const int c = lane + 32*i;
        const float y = (v[i] - mu) * inv * w[c] + b[c];
        g_xnf[t*EDIM + c] = y;
        g_xnb[t*EDIM + c] = __float2bfloat16(y);
    }
}

// ---------------- GEMM: C = sigmoid(A @ W^T + ct) * xn -> fp32 ----------------
#define BM_T 128
#define BK_T 32
#define LDT  (BK_T + 8)
#define STAGES 5

__device__ __forceinline__ void ldm4(uint32_t a, uint32_t& r0, uint32_t& r1, uint32_t& r2, uint32_t& r3) {
    asm volatile("ldmatrix.sync.aligned.m8n8.x4.shared.b16 {%0,%1,%2,%3}, [%4];"
                 : "=r"(r0), "=r"(r1), "=r"(r2), "=r"(r3) : "r"(a));
}
__device__ __forceinline__ void ldm2(uint32_t a, uint32_t& r0, uint32_t& r1) {
    asm volatile("ldmatrix.sync.aligned.m8n8.x2.shared.b16 {%0,%1}, [%2];"
                 : "=r"(r0), "=r"(r1) : "r"(a));
}
__device__ __forceinline__ void mma16816(float* c, const uint32_t* a, const uint32_t* b) {
    asm volatile("mma.sync.aligned.m16n8k16.row.col.f32.bf16.bf16.f32 "
                 "{%0,%1,%2,%3}, {%4,%5,%6,%7}, {%8,%9}, {%0,%1,%2,%3};"
                 : "+f"(c[0]), "+f"(c[1]), "+f"(c[2]), "+f"(c[3])
                 : "r"(a[0]), "r"(a[1]), "r"(a[2]), "r"(a[3]), "r"(b[0]), "r"(b[1]));
}

template<int BN>
__global__ __launch_bounds__(512, 1) void gemm_k(
    const __nv_bfloat16* __restrict__ A, const __nv_bfloat16* __restrict__ W,
    const float* __restrict__ bias, const float* __restrict__ xnf,
    float* __restrict__ Cout, int M, int N, int K)
{
    constexpr int NIW  = BN / 32;
    constexpr int ASTG = BM_T * LDT;
    constexpr int BSTG = BN * LDT;

    extern __shared__ __align__(16) __nv_bfloat16 smem[];
    __nv_bfloat16* Asm = smem;
    __nv_bfloat16* Bsm = smem + STAGES * ASTG;

    const int tid  = threadIdx.x;
    const int lane = tid & 31;
    const int warp = tid >> 5;
    const int wr = warp & 3;
    const int wc = warp >> 2;

    const uint32_t sA = (uint32_t)__cvta_generic_to_shared(Asm);
    const uint32_t sB = (uint32_t)__cvta_generic_to_shared(Bsm);
    const size_t Arow0 = (size_t)blockIdx.x * BM_T;
    const size_t Brow0 = (size_t)blockIdx.y * BN;
    const int KT = K / BK_T;

    auto load_st = [&](int kt, int buf) {
        const __nv_bfloat16* Ag = A + Arow0 * K + (size_t)kt * BK_T;
        const uint32_t sa = sA + buf * (ASTG * 2);
        for (int id = tid; id < BM_T * 4; id += 512) {
            const int r = id >> 2, c = (id & 3) * 8;
            cp16(sa + (r * LDT + c) * 2, Ag + (size_t)r * K + c);
        }
        const __nv_bfloat16* Bg = W + Brow0 * K + (size_t)kt * BK_T;
        const uint32_t sb = sB + buf * (BSTG * 2);
        for (int id = tid; id < BN * 4; id += 512) {
            const int r = id >> 2, c = (id & 3) * 8;
            cp16(sb + (r * LDT + c) * 2, Bg + (size_t)r * K + c);
        }
        asm volatile("cp.async.commit_group;");
    };

    float acc[2][NIW][4];
    #pragma unroll
    for (int mi = 0; mi < 2; mi++)
        #pragma unroll
        for (int ni = 0; ni < NIW; ni++)
            #pragma unroll
            for (int e = 0; e < 4; e++) acc[mi][ni][e] = 0.f;

    load_st(0, 0);
    load_st(1, 1);
    load_st(2, 2);
    load_st(3, 3);

    for (int kt = 0; kt < KT; kt++) {
        const int rem = KT - 1 - kt;
        if (rem >= 3)      asm volatile("cp.async.wait_group 3;");
        else if (rem == 2) asm volatile("cp.async.wait_group 2;");
        else if (rem == 1) asm volatile("cp.async.wait_group 1;");
        else               asm volatile("cp.async.wait_group 0;");
        __syncthreads();

        if (kt + 4 < KT) load_st(kt + 4, (kt + 4) % STAGES);

        const int buf = kt % STAGES;
        const uint32_t baseA = sA + buf * (ASTG * 2);
        const uint32_t baseB = sB + buf * (BSTG * 2);
        #pragma unroll
        for (int ks = 0; ks < 2; ks++) {
            uint32_t af[2][4];
            #pragma unroll
            for (int mi = 0; mi < 2; mi++) {
                const int row = wr * 32 + mi * 16 + (lane & 15);
                const int col = ks * 16 + (lane >> 4) * 8;
                ldm4(baseA + (row * LDT + col) * 2, af[mi][0], af[mi][1], af[mi][2], af[mi][3]);
            }
            uint32_t bf[NIW][2];
            #pragma unroll
            for (int np = 0; np < NIW / 2; np++) {
                const int row = wc * (BN / 4) + np * 16 + (lane & 7) + ((lane >> 4) << 3);
                const int col = ks * 16 + (((lane >> 3) & 1) << 3);
                ldm4(baseB + (row * LDT + col) * 2,
                     bf[2*np][0], bf[2*np][1], bf[2*np+1][0], bf[2*np+1][1]);
            }
            if (NIW & 1) {
                const int l = lane & 15;
                const int row = wc * (BN / 4) + (NIW - 1) * 8 + (l & 7);
                const int col = ks * 16 + ((l >> 3) << 3);
                ldm2(baseB + (row * LDT + col) * 2, bf[NIW-1][0], bf[NIW-1][1]);
            }
            #pragma unroll
            for (int mi = 0; mi < 2; mi++)
                #pragma unroll
                for (int ni = 0; ni < NIW; ni++)
                    mma16816(acc[mi][ni], af[mi], bf[ni]);
        }
    }

    const size_t mb = Arow0 + wr * 32;
    const int nb = (int)Brow0 + wc * (BN / 4);
    #pragma unroll
    for (int mi = 0; mi < 2; mi++) {
        #pragma unroll
        for (int ni = 0; ni < NIW; ni++) {
            const size_t m0 = mb + mi * 16 + (lane >> 2);
            const int n0 = nb + ni * 8 + (lane & 3) * 2;
            #pragma unroll
            for (int e = 0; e < 4; e++) {
                const size_t m = m0 + ((e >= 2) ? 8 : 0);
                const int n = n0 + (e & 1);
                const float v = acc[mi][ni][e] + bias[n];
                const float sg = 1.f / (1.f + __expf(-v));
                Cout[m * N + n] = sg * xnf[m * N + n];
            }
        }
    }
}

// ---------------- head GEMM: fp32, M=65536 N=32 K=320 ----------------
__global__ __launch_bounds__(256, 2) void head_kernel(
    const float* __restrict__ A, const float* __restrict__ W,
    const float* __restrict__ bias, float* __restrict__ out)
{
    __shared__ float ws[EDIM * CDIM];
    __shared__ float as[32 * 128];

    const int tid = threadIdx.x;
    for (int i = tid; i < EDIM * CDIM; i += 256) {
        const int c = i & 31;
        const int k = i >> 5;
        ws[k * CDIM + c] = W[c * EDIM + k];
    }

    const size_t row0 = (size_t)blockIdx.x * 128;
    const int rg = tid >> 3;
    const int cg = tid & 7;

    float acc[4][4];
    #pragma unroll
    for (int i = 0; i < 4; i++)
        #pragma unroll
        for (int j = 0; j < 4; j++) acc[i][j] = 0.f;

    for (int k0 = 0; k0 < EDIM; k0 += 32) {
        __syncthreads();
        #pragma unroll
        for (int i = 0; i < 4; i++) {
            const int idx = tid + 256 * i;
            const int r  = idx & 127;
            const int kq = idx >> 7;
            const float4 v = *(const float4*)(A + (row0 + r) * EDIM + k0 + kq * 4);
            as[(kq * 4 + 0) * 128 + r] = v.x;
            as[(kq * 4 + 1) * 128 + r] = v.y;
            as[(kq * 4 + 2) * 128 + r] = v.z;
            as[(kq * 4 + 3) * 128 + r] = v.w;
        }
        __syncthreads();
        #pragma unroll
        for (int k = 0; k < 32; k++) {
            const float4 av = *(const float4*)(as + k * 128 + rg * 4);
            const float4 bv = *(const float4*)(ws + (k0 + k) * CDIM + cg * 4);
            acc[0][0] += av.x * bv.x; acc[0][1] += av.x * bv.y;
            acc[0][2] += av.x * bv.z; acc[0][3] += av.x * bv.w;
            acc[1][0] += av.y * bv.x; acc[1][1] += av.y * bv.y;
            acc[1][2] += av.y * bv.z; acc[1][3] += av.y * bv.w;
            acc[2][0] += av.z * bv.x; acc[2][1] += av.z * bv.y;
            acc[2][2] += av.z * bv.z; acc[2][3] += av.z * bv.w;
            acc[3][0] += av.w * bv.x; acc[3][1] += av.w * bv.y;
            acc[3][2] += av.w * bv.z; acc[3][3] += av.w * bv.w;
        }
    }

    const float4 bv = *(const float4*)(bias + cg * 4);
    #pragma unroll
    for (int i = 0; i < 4; i++) {
        float4 o;
        o.x = acc[i][0] + bv.x;
        o.y = acc[i][1] + bv.y;
        o.z = acc[i][2] + bv.z;
        o.w = acc[i][3] + bv.w;
        *(float4*)(out + (row0 + rg * 4 + i) * CDIM + cg * 4) = o;
    }
}

// ---------------- launch ----------------
extern "C" void kernel_launch(void* const* d_in, const int* in_sizes, int n_in,
                              void* d_out, int out_size)
{
    (void)in_sizes; (void)n_in; (void)out_size;
    const float* x       = (const float*)d_in[0];
    const float* snr     = (const float*)d_in[1];
    const float* norm_w  = (const float*)d_in[2];
    const float* norm_b  = (const float*)d_in[3];
    const float* sm0_w   = (const float*)d_in[4];
    const float* sm0_b   = (const float*)d_in[5];
    const float* smm_w   = (const float*)d_in[6];
    const float* smm_b   = (const float*)d_in[7];
    const float* sml_w   = (const float*)d_in[8];
    const float* sml_b   = (const float*)d_in[9];
    const float* bm_w1   = (const float*)d_in[10];
    const float* bm_b1   = (const float*)d_in[11];
    const float* bm_w2   = (const float*)d_in[12];
    const float* bm_b2   = (const float*)d_in[13];
    const float* bm_w3   = (const float*)d_in[14];
    const float* bm_b3   = (const float*)d_in[15];
    const float* head_w  = (const float*)d_in[16];
    const float* head_b  = (const float*)d_in[17];

    float *p_mat, *p_ct, *p_xnf, *p_xgf;
    __nv_bfloat16 *p_wtb, *p_xnb;
    cudaGetSymbolAddress((void**)&p_mat, g_mat);
    cudaGetSymbolAddress((void**)&p_ct,  g_ct);
    cudaGetSymbolAddress((void**)&p_wtb, g_wtb);
    cudaGetSymbolAddress((void**)&p_xnf, g_xnf);
    cudaGetSymbolAddress((void**)&p_xnb, g_xnb);
    cudaGetSymbolAddress((void**)&p_xgf, g_xgf);

    constexpr int SMEM_G = STAGES * (BM_T + 160) * LDT * 2;  // 115200 B
    cudaFuncSetAttribute(gemm_k<160>, cudaFuncAttributeMaxDynamicSharedMemorySize, SMEM_G);

    // ---- token-independent precompute ----
    bm_kernel<<<NLAYER, 512>>>(snr, bm_w1, bm_b1, bm_w2, bm_b2, bm_w3, bm_b3);
    materialize_kernel<<<1024, 256>>>(sm0_w, sm0_b, smm_w, smm_b, sml_w, sml_b);

    // LayerNorm of tokens
    ln_kernel<<<MTOK/8, 256>>>(x, norm_w, norm_b);

    // ---- balanced-tree composition of 8 augmented matrices ----
    mm3<0><<<dim3(ADIM/64, ADIM/64, 4), 256>>>(p_mat + 0*MS, 2*MS, p_mat + 1*MS, 2*MS, p_mat + 8*MS, MS);
    mm3<0><<<dim3(ADIM/64, ADIM/64, 2), 256>>>(p_mat + 8*MS, 2*MS, p_mat + 9*MS, 2*MS, p_mat + 12*MS, MS);
    // final level writes g_wtb / g_ct directly; only rows/cols < 321 matter -> 6x6 grid
    mm3<1><<<dim3(6, 6, 1), 256>>>(p_mat + 12*MS, 0, p_mat + 13*MS, 0, nullptr, 0);

    // ---- token compute: ONE fused E->E GEMM, then head ----
    gemm_k<160><<<dim3(MTOK/BM_T, EDIM/160), 512, SMEM_G>>>(
        p_xnb, p_wtb, p_ct, p_xnf, p_xgf, MTOK, EDIM, EDIM);
    head_kernel<<<MTOK/128, 256>>>(p_xgf, head_w, head_b, (float*)d_out);
}

// round 15
// speedup vs baseline: 13.0381x; 1.1553x over previous
#include <cuda_runtime.h>
#include <cuda_bf16.h>
#include <cstdint>

// ---------------- problem constants ----------------
#define BATCH 64
#define LSEQ  1024
#define EDIM  320
#define HDIM  480
#define CDIM  32
#define NLAYER 7
#define MTOK  (BATCH*LSEQ)   // 65536
#define ADIM  512            // augmented matrix size (481 used, padded)
#define MS    (ADIM*ADIM)    // elements per slot

// ---------------- device scratch ----------------
__device__ float          g_bm[NLAYER*HDIM];
__device__ __align__(1024) float g_mat[14*MS];
__device__ float          g_ct[EDIM];
__device__ __nv_bfloat16  g_wtb[EDIM*EDIM];

__device__ __forceinline__ void cp16(uint32_t s, const void* g) {
    asm volatile("cp.async.cg.shared.global [%0], [%1], 16;" :: "r"(s), "l"(g));
}

// ---------------- bm: one CTA per layer, warp-per-row coalesced ----------------
__global__ __launch_bounds__(512) void bm_kernel(
    const float* __restrict__ snr,
    const float* __restrict__ w1, const float* __restrict__ b1,
    const float* __restrict__ w2, const float* __restrict__ b2,
    const float* __restrict__ w3, const float* __restrict__ b3)
{
    const int i = blockIdx.x;
    __shared__ float h1[HDIM];
    __shared__ float h2[HDIM];
    const int tid  = threadIdx.x;
    const int warp = tid >> 5;
    const int lane = tid & 31;
    const float s = snr[0];

    for (int j = tid; j < HDIM; j += 512)
        h1[j] = fmaxf(0.f, s * w1[i*HDIM + j] + b1[i*HDIM + j]);
    __syncthreads();

    for (int j = warp; j < HDIM; j += 16) {
        const float* w = w2 + ((size_t)i*HDIM + j) * HDIM;
        float acc = 0.f;
        for (int k = lane; k < HDIM; k += 32) acc += w[k] * h1[k];
        #pragma unroll
        for (int o = 16; o > 0; o >>= 1) acc += __shfl_xor_sync(0xffffffffu, acc, o);
        if (lane == 0) h2[j] = fmaxf(0.f, acc + b2[i*HDIM + j]);
    }
    __syncthreads();

    for (int j = warp; j < HDIM; j += 16) {
        const float* w = w3 + ((size_t)i*HDIM + j) * HDIM;
        float acc = 0.f;
        for (int k = lane; k < HDIM; k += 32) acc += w[k] * h2[k];
        #pragma unroll
        for (int o = 16; o > 0; o >>= 1) acc += __shfl_xor_sync(0xffffffffu, acc, o);
        if (lane == 0) g_bm[i*HDIM + j] = 1.f / (1.f + expf(-(acc + b3[i*HDIM + j])));
    }
}

// ---------------- materialize the 8 augmented matrices ----------------
__global__ void materialize_kernel(
    const float* __restrict__ sm0_w, const float* __restrict__ sm0_b,
    const float* __restrict__ smm_w, const float* __restrict__ smm_b,
    const float* __restrict__ sml_w, const float* __restrict__ sml_b)
{
    const long stride = (long)gridDim.x * blockDim.x;
    for (long idx = (long)blockIdx.x * blockDim.x + threadIdx.x; idx < 8L*MS; idx += stride) {
        const int slot = (int)(idx / MS);
        const int e = (int)(idx - (long)slot * MS);
        const int r = e >> 9;
        const int c = e & 511;
        float v = 0.f;
        if (slot == 0) {               // Wl~
            if (r < EDIM) {
                if (c < HDIM)       v = sml_w[r*HDIM + c];
                else if (c == HDIM) v = sml_b[r];
            } else if (r == EDIM && c == HDIM) v = 1.f;
        } else if (slot <= 6) {        // A_i~, i = 7-slot
            const int i = 7 - slot;
            if (r < HDIM) {
                const float g = g_bm[i*HDIM + r];
                if (c < HDIM)       v = g * smm_w[((size_t)(i-1)*HDIM + r)*HDIM + c];
                else if (c == HDIM) v = g * smm_b[(i-1)*HDIM + r];
            } else if (r == HDIM && c == HDIM) v = 1.f;
        } else {                       // M0~
            if (r < HDIM) {
                const float g = g_bm[r];
                if (c < EDIM)       v = g * sm0_w[r*EDIM + c];
                else if (c == EDIM) v = g * sm0_b[r];
            } else if (r == HDIM && c == EDIM) v = 1.f;
        }
        g_mat[idx] = v;
    }
}

// ---------------- batched 512x512x512 fp32 GEMM (tree) ----------------
#define MM_STG 4
template<int FIN>
__global__ __launch_bounds__(256) void mm3(
    const float* __restrict__ Ab, int Asz,
    const float* __restrict__ Bb, int Bsz,
    float* __restrict__ Cb, int Csz)
{
    const float* A = Ab + (size_t)blockIdx.z * Asz;
    const float* B = Bb + (size_t)blockIdx.z * Bsz;
    float*       C = Cb + (size_t)blockIdx.z * Csz;

    __shared__ __align__(16) float As[MM_STG][64][36];
    __shared__ __align__(16) float Bs[MM_STG][32][68];

    const int tid = threadIdx.x;
    const int tx = tid & 15;
    const int ty = tid >> 4;
    const int r0 = blockIdx.y * 64, c0 = blockIdx.x * 64;

    const uint32_t sA = (uint32_t)__cvta_generic_to_shared(&As[0][0][0]);
    const uint32_t sB = (uint32_t)__cvta_generic_to_shared(&Bs[0][0][0]);

    auto load_st = [&](int kt, int buf) {
        #pragma unroll
        for (int id = tid; id < 512; id += 256) {
            const int row = id >> 3, kc = (id & 7) * 4;
            cp16(sA + ((buf*64 + row)*36 + kc)*4,
                 A + (size_t)(r0 + row) * ADIM + kt*32 + kc);
        }
        #pragma unroll
        for (int id = tid; id < 512; id += 256) {
            const int row = id >> 4, nc = (id & 15) * 4;
            cp16(sB + ((buf*32 + row)*68 + nc)*4,
                 B + (size_t)(kt*32 + row) * ADIM + c0 + nc);
        }
        asm volatile("cp.async.commit_group;");
    };

    float acc[4][4];
    #pragma unroll
    for (int i = 0; i < 4; i++)
        #pragma unroll
        for (int j = 0; j < 4; j++) acc[i][j] = 0.f;

    load_st(0, 0);
    load_st(1, 1);
    load_st(2, 2);

    const int KT = ADIM / 32;          // 16
    for (int kt = 0; kt < KT; kt++) {
        const int rem = KT - 1 - kt;
        if (rem >= 2)      asm volatile("cp.async.wait_group 2;");
        else if (rem == 1) asm volatile("cp.async.wait_group 1;");
        else               asm volatile("cp.async.wait_group 0;");
        __syncthreads();

        if (kt + 3 < KT) load_st(kt + 3, (kt + 3) & 3);

        const int buf = kt & 3;
        #pragma unroll
        for (int k = 0; k < 32; k++) {
            const float4 bv = *(const float4*)&Bs[buf][k][tx*4];
            const float a0 = As[buf][ty*4+0][k];
            const float a1 = As[buf][ty*4+1][k];
            const float a2 = As[buf][ty*4+2][k];
            const float a3 = As[buf][ty*4+3][k];
            acc[0][0] += a0*bv.x; acc[0][1] += a0*bv.y; acc[0][2] += a0*bv.z; acc[0][3] += a0*bv.w;
            acc[1][0] += a1*bv.x; acc[1][1] += a1*bv.y; acc[1][2] += a1*bv.z; acc[1][3] += a1*bv.w;
            acc[2][0] += a2*bv.x; acc[2][1] += a2*bv.y; acc[2][2] += a2*bv.z; acc[2][3] += a2*bv.w;
            acc[3][0] += a3*bv.x; acc[3][1] += a3*bv.y; acc[3][2] += a3*bv.z; acc[3][3] += a3*bv.w;
        }
        __syncthreads();
    }

    if (FIN == 0) {
        #pragma unroll
        for (int i = 0; i < 4; i++) {
            float4 o;
            o.x = acc[i][0]; o.y = acc[i][1]; o.z = acc[i][2]; o.w = acc[i][3];
            *(float4*)(C + (size_t)(r0 + ty*4 + i) * ADIM + c0 + tx*4) = o;
        }
    } else {
        const int c = c0 + tx*4;
        #pragma unroll
        for (int i = 0; i < 4; i++) {
            const int r = r0 + ty*4 + i;
            if (r < EDIM) {
                if (c + 3 < EDIM) {
                    __nv_bfloat162 h0 = __floats2bfloat162_rn(acc[i][0], acc[i][1]);
                    __nv_bfloat162 h1 = __floats2bfloat162_rn(acc[i][2], acc[i][3]);
                    uint2 pk;
                    pk.x = *(const uint32_t*)&h0;
                    pk.y = *(const uint32_t*)&h1;
                    *(uint2*)(&g_wtb[(size_t)r * EDIM + c]) = pk;
                } else if (c == EDIM) {
                    g_ct[r] = acc[i][0];
                }
            }
        }
    }
}

// ---------------- fused token kernel ----------------
// One CTA = 128 tokens, full pipeline:
//   LN (warp/row) -> xn bf16 resident in smem + mu/inv
//   z = xn @ Wt^T (tcgen-legacy HMMA, B streamed via cp.async ring)
//   xg = sigmoid(z + ct) * xn_fp32 (recomputed exactly from x, mu, inv)
//   out = xg @ head_w^T + head_b   (fp32 FFMA from smem)
#define BK_T 32
#define LDT  40
#define KT_F (EDIM / BK_T)    // 10
#define F_STG 4
// smem layout (bytes)
#define OFF_MU   0
#define OFF_INV  512
#define OFF_A    1024                              // 10*128*40*2 = 102400
#define OFF_B    (OFF_A + KT_F*128*LDT*2)          // 103424 ; 4 stages x 25600
#define OFF_XG   1024                              // fp32 [320][132] = 168960 (reuses A+B)
#define OFF_WH   (OFF_XG + EDIM*132*4)             // 169984 ; 320*32*4 = 40960
#define SMEM_F   (OFF_WH + EDIM*CDIM*4)            // 210944

__device__ __forceinline__ void ldm4(uint32_t a, uint32_t& r0, uint32_t& r1, uint32_t& r2, uint32_t& r3) {
    asm volatile("ldmatrix.sync.aligned.m8n8.x4.shared.b16 {%0,%1,%2,%3}, [%4];"
                 : "=r"(r0), "=r"(r1), "=r"(r2), "=r"(r3) : "r"(a));
}
__device__ __forceinline__ void mma16816(float* c, const uint32_t* a, const uint32_t* b) {
    asm volatile("mma.sync.aligned.m16n8k16.row.col.f32.bf16.bf16.f32 "
                 "{%0,%1,%2,%3}, {%4,%5,%6,%7}, {%8,%9}, {%0,%1,%2,%3};"
                 : "+f"(c[0]), "+f"(c[1]), "+f"(c[2]), "+f"(c[3])
                 : "r"(a[0]), "r"(a[1]), "r"(a[2]), "r"(a[3]), "r"(b[0]), "r"(b[1]));
}

__global__ __launch_bounds__(512, 1) void fused_k(
    const float* __restrict__ x,
    const float* __restrict__ nw, const float* __restrict__ nb,
    const __nv_bfloat16* __restrict__ Wt,
    const float* __restrict__ hw, const float* __restrict__ hb,
    float* __restrict__ out)
{
    extern __shared__ __align__(16) char smem[];
    const uint32_t sbase = (uint32_t)__cvta_generic_to_shared(smem);
    float* s_mu  = (float*)(smem + OFF_MU);
    float* s_inv = (float*)(smem + OFF_INV);
    __nv_bfloat16* s_xn = (__nv_bfloat16*)(smem + OFF_A);
    float* s_xgT = (float*)(smem + OFF_XG);
    float* s_wh  = (float*)(smem + OFF_WH);

    const int tid  = threadIdx.x;
    const int lane = tid & 31;
    const int warp = tid >> 5;
    const size_t row0 = (size_t)blockIdx.x * 128;

    // ---- kick off B prologue first (overlaps with LN) ----
    auto load_B = [&](int kt, int buf) {
        const uint32_t sb = sbase + OFF_B + (uint32_t)buf * (EDIM * LDT * 2);
        #pragma unroll
        for (int id = tid; id < EDIM * 4; id += 512) {
            const int r = id >> 2, c = (id & 3) * 8;
            cp16(sb + (r * LDT + c) * 2, Wt + (size_t)r * EDIM + kt * BK_T + c);
        }
        asm volatile("cp.async.commit_group;");
    };
    load_B(0, 0);
    load_B(1, 1);
    load_B(2, 2);

    // ---- phase 1: LayerNorm, write bf16 xn into A staging layout ----
    {
        #pragma unroll
        for (int r = 0; r < 8; r++) {
            const int row = warp * 8 + r;
            const float* xp = x + (row0 + row) * EDIM;
            float v[10];
            float s = 0.f, s2 = 0.f;
            #pragma unroll
            for (int i = 0; i < 10; i++) {
                v[i] = xp[lane + 32*i];
                s  += v[i];
                s2 += v[i]*v[i];
            }
            #pragma unroll
            for (int o = 16; o > 0; o >>= 1) {
                s  += __shfl_xor_sync(0xffffffffu, s,  o);
                s2 += __shfl_xor_sync(0xffffffffu, s2, o);
            }
            const float mu  = s  * (1.f/EDIM);
            const float var = s2 * (1.f/EDIM) - mu*mu;
            const float inv = 1.f / sqrtf(var + 1e-5f);
            if (lane == 0) { s_mu[row] = mu; s_inv[row] = inv; }
            #pragma unroll
            for (int i = 0; i < 10; i++) {
                const int c = lane + 32*i;
                const float y = (v[i] - mu) * inv * nw[c] + nb[c];
                // chunk i, row, offset lane
                s_xn[(i*128 + row)*LDT + lane] = __float2bfloat16(y);
            }
        }
    }
    __syncthreads();

    // ---- phase 2: MMA mainloop; A resident, B 4-stage ring ----
    const int wr = warp & 3;   // M
    const int wc = warp >> 2;  // N (80 cols each)
    float acc[2][10][4];
    #pragma unroll
    for (int mi = 0; mi < 2; mi++)
        #pragma unroll
        for (int ni = 0; ni < 10; ni++)
            #pragma unroll
            for (int e = 0; e < 4; e++) acc[mi][ni][e] = 0.f;

    for (int kt = 0; kt < KT_F; kt++) {
        const int rem = KT_F - 1 - kt;
        if (rem >= 3)      asm volatile("cp.async.wait_group 3;");
        else if (rem == 2) asm volatile("cp.async.wait_group 2;");
        else if (rem == 1) asm volatile("cp.async.wait_group 1;");
        else               asm volatile("cp.async.wait_group 0;");
        __syncthreads();

        if (kt + 3 < KT_F) load_B(kt + 3, (kt + 3) & 3);

        const uint32_t baseA = sbase + OFF_A + (uint32_t)kt * (128 * LDT * 2);
        const uint32_t baseB = sbase + OFF_B + (uint32_t)(kt & 3) * (EDIM * LDT * 2);
        #pragma unroll
        for (int ks = 0; ks < 2; ks++) {
            uint32_t af[2][4];
            #pragma unroll
            for (int mi = 0; mi < 2; mi++) {
                const int row = wr * 32 + mi * 16 + (lane & 15);
                const int col = ks * 16 + (lane >> 4) * 8;
                ldm4(baseA + (row * LDT + col) * 2, af[mi][0], af[mi][1], af[mi][2], af[mi][3]);
            }
            #pragma unroll
            for (int np = 0; np < 5; np++) {
                uint32_t b0, b1, b2, b3;
                const int row = wc * 80 + np * 16 + (lane & 7) + ((lane >> 4) << 3);
                const int col = ks * 16 + (((lane >> 3) & 1) << 3);
                ldm4(baseB + (row * LDT + col) * 2, b0, b1, b2, b3);
                uint32_t bfa[2] = {b0, b1};
                uint32_t bfb[2] = {b2, b3};
                #pragma unroll
                for (int mi = 0; mi < 2; mi++) {
                    mma16816(acc[mi][2*np],   af[mi], bfa);
                    mma16816(acc[mi][2*np+1], af[mi], bfb);
                }
            }
        }
        __syncthreads();
    }

    // ---- phase 3: epilogue: sigmoid gate, store xg transposed fp32 ----
    // (A/B smem regions are dead after the final __syncthreads above)
    {
        const int mb = wr * 32;
        const int nbase = wc * 80;
        #pragma unroll
        for (int ni = 0; ni < 10; ni++) {
            #pragma unroll
            for (int c2 = 0; c2 < 2; c2++) {
                const int n = nbase + ni * 8 + (lane & 3) * 2 + c2;
                const float ctv = g_ct[n];
                const float nwv = nw[n];
                const float nbv = nb[n];
                #pragma unroll
                for (int mi = 0; mi < 2; mi++) {
                    #pragma unroll
                    for (int eh = 0; eh < 2; eh++) {
                        const int m = mb + mi * 16 + (lane >> 2) + eh * 8;
                        const float z = acc[mi][ni][eh * 2 + c2] + ctv;
                        const float sg = 1.f / (1.f + __expf(-z));
                        const float xv = x[(row0 + m) * EDIM + n];
                        const float xn = (xv - s_mu[m]) * s_inv[m] * nwv + nbv;
                        s_xgT[n * 132 + m] = sg * xn;
                    }
                }
            }
        }
    }
    // load head weights transposed into smem (disjoint region)
    for (int i = tid; i < EDIM * CDIM; i += 512) {
        const int c = i & 31;
        const int k = i >> 5;
        s_wh[k * CDIM + c] = hw[c * EDIM + k];
    }
    __syncthreads();

    // ---- phase 4: head GEMM out[128,32] = xg @ hw^T + hb ----
    {
        const int rg = tid >> 4;      // 0..31 -> 4 rows
        const int cg = tid & 15;      // 0..15 -> 2 cols
        float a2[4][2];
        #pragma unroll
        for (int i = 0; i < 4; i++) { a2[i][0] = 0.f; a2[i][1] = 0.f; }
        #pragma unroll 4
        for (int k = 0; k < EDIM; k++) {
            const float4 av = *(const float4*)&s_xgT[k * 132 + rg * 4];
            const float b0 = s_wh[k * CDIM + cg * 2];
            const float b1 = s_wh[k * CDIM + cg * 2 + 1];
            a2[0][0] += av.x * b0; a2[0][1] += av.x * b1;
            a2[1][0] += av.y * b0; a2[1][1] += av.y * b1;
            a2[2][0] += av.z * b0; a2[2][1] += av.z * b1;
            a2[3][0] += av.w * b0; a2[3][1] += av.w * b1;
        }
        const float hb0 = hb[cg * 2];
        const float hb1 = hb[cg * 2 + 1];
        #pragma unroll
        for (int i = 0; i < 4; i++) {
            const size_t m = row0 + rg * 4 + i;
            out[m * CDIM + cg * 2]     = a2[i][0] + hb0;
            out[m * CDIM + cg * 2 + 1] = a2[i][1] + hb1;
        }
    }
}

// ---------------- launch ----------------
extern "C" void kernel_launch(void* const* d_in, const int* in_sizes, int n_in,
                              void* d_out, int out_size)
{
    (void)in_sizes; (void)n_in; (void)out_size;
    const float* x       = (const float*)d_in[0];
    const float* snr     = (const float*)d_in[1];
    const float* norm_w  = (const float*)d_in[2];
    const float* norm_b  = (const float*)d_in[3];
    const float* sm0_w   = (const float*)d_in[4];
    const float* sm0_b   = (const float*)d_in[5];
    const float* smm_w   = (const float*)d_in[6];
    const float* smm_b   = (const float*)d_in[7];
    const float* sml_w   = (const float*)d_in[8];
    const float* sml_b   = (const float*)d_in[9];
    const float* bm_w1   = (const float*)d_in[10];
    const float* bm_b1   = (const float*)d_in[11];
    const float* bm_w2   = (const float*)d_in[12];
    const float* bm_b2   = (const float*)d_in[13];
    const float* bm_w3   = (const float*)d_in[14];
    const float* bm_b3   = (const float*)d_in[15];
    const float* head_w  = (const float*)d_in[16];
    const float* head_b  = (const float*)d_in[17];

    float *p_mat;
    __nv_bfloat16 *p_wtb;
    cudaGetSymbolAddress((void**)&p_mat, g_mat);
    cudaGetSymbolAddress((void**)&p_wtb, g_wtb);

    cudaFuncSetAttribute(fused_k, cudaFuncAttributeMaxDynamicSharedMemorySize, SMEM_F);

    // ---- token-independent precompute ----
    bm_kernel<<<NLAYER, 512>>>(snr, bm_w1, bm_b1, bm_w2, bm_b2, bm_w3, bm_b3);
    materialize_kernel<<<1024, 256>>>(sm0_w, sm0_b, smm_w, smm_b, sml_w, sml_b);

    // ---- balanced-tree composition ----
    mm3<0><<<dim3(ADIM/64, ADIM/64, 4), 256>>>(p_mat + 0*MS, 2*MS, p_mat + 1*MS, 2*MS, p_mat + 8*MS, MS);
    mm3<0><<<dim3(ADIM/64, ADIM/64, 2), 256>>>(p_mat + 8*MS, 2*MS, p_mat + 9*MS, 2*MS, p_mat + 12*MS, MS);
    mm3<1><<<dim3(6, 6, 1), 256>>>(p_mat + 12*MS, 0, p_mat + 13*MS, 0, nullptr, 0);

    // ---- ONE fused token kernel: LN + gate GEMM + sigmoid + head ----
    fused_k<<<MTOK/128, 512, SMEM_F>>>(x, norm_w, norm_b, p_wtb, head_w, head_b,
                                       (float*)d_out);
}